// round 6
// baseline (speedup 1.0000x reference)
#include <cuda_runtime.h>
#include <cuda_bf16.h>
#include <cstdint>
#include <cstddef>
#include <math.h>

#define DIMD 1024
#define HID  4096
#define NEXP 8
#define TOPK 3
#define NTOK 4096
#define MAXROWS (NTOK * TOPK + 512)

// ---------------- device scratch (allocations forbidden) --------------------
__device__ __nv_bfloat16 g_XH[(size_t)NTOK * DIMD];
__device__ __nv_bfloat16 g_XL[(size_t)NTOK * DIMD];
__device__ __nv_bfloat16 g_W12H[(size_t)NEXP * DIMD * 2 * HID];
__device__ __nv_bfloat16 g_W12L[(size_t)NEXP * DIMD * 2 * HID];
__device__ __nv_bfloat16 g_W3H[(size_t)NEXP * HID * DIMD];
__device__ __nv_bfloat16 g_W3L[(size_t)NEXP * HID * DIMD];
__device__ __nv_bfloat16 g_HIDH[(size_t)MAXROWS * HID];
__device__ __nv_bfloat16 g_HIDL[(size_t)MAXROWS * HID];
__device__ float g_OUTP[(size_t)MAXROWS * DIMD];
__device__ int   g_counts[NEXP];
__device__ int   g_offs[NEXP];
__device__ int   g_rows[NEXP * NTOK];
__device__ int   g_tok_e[NTOK * TOPK];
__device__ int   g_tok_pos[NTOK * TOPK];
__device__ float g_tok_w[NTOK * TOPK];
__device__ float g_aux;

// ---------------- helpers ---------------------------------------------------
__device__ __forceinline__ uint32_t smem_u32(const void* p) {
    uint32_t a;
    asm("{ .reg .u64 t; cvta.to.shared.u64 t, %1; cvt.u32.u64 %0, t; }" : "=r"(a) : "l"(p));
    return a;
}
__device__ __forceinline__ void cpa16(uint32_t s, const void* g) {
    asm volatile("cp.async.cg.shared.global [%0], [%1], 16;" :: "r"(s), "l"(g));
}
__device__ __forceinline__ void cp_commit() {
    asm volatile("cp.async.commit_group;" ::: "memory");
}
__device__ __forceinline__ void cp_wait1() {
    asm volatile("cp.async.wait_group 1;" ::: "memory");
}
__device__ __forceinline__ void cp_wait2() {
    asm volatile("cp.async.wait_group 2;" ::: "memory");
}
__device__ __forceinline__ void ldsm4(uint32_t* r, uint32_t a) {
    asm volatile("ldmatrix.sync.aligned.m8n8.x4.shared.b16 {%0,%1,%2,%3}, [%4];"
                 : "=r"(r[0]), "=r"(r[1]), "=r"(r[2]), "=r"(r[3]) : "r"(a));
}
__device__ __forceinline__ void ldsm4t(uint32_t* r, uint32_t a) {
    asm volatile("ldmatrix.sync.aligned.m8n8.x4.trans.shared.b16 {%0,%1,%2,%3}, [%4];"
                 : "=r"(r[0]), "=r"(r[1]), "=r"(r[2]), "=r"(r[3]) : "r"(a));
}
__device__ __forceinline__ void mma16816(float* c, const uint32_t* a, const uint32_t* b) {
    asm volatile("mma.sync.aligned.m16n8k16.row.col.f32.bf16.bf16.f32 "
                 "{%0,%1,%2,%3}, {%4,%5,%6,%7}, {%8,%9}, {%0,%1,%2,%3};"
                 : "+f"(c[0]), "+f"(c[1]), "+f"(c[2]), "+f"(c[3])
                 : "r"(a[0]), "r"(a[1]), "r"(a[2]), "r"(a[3]), "r"(b[0]), "r"(b[1]));
}
__device__ __forceinline__ uint32_t pack2(__nv_bfloat16 a, __nv_bfloat16 b) {
    return (uint32_t)__bfloat16_as_ushort(a) | ((uint32_t)__bfloat16_as_ushort(b) << 16);
}
__device__ __forceinline__ void split4(float4 v, uint2& hv, uint2& lv) {
    __nv_bfloat16 h0 = __float2bfloat16(v.x), h1 = __float2bfloat16(v.y);
    __nv_bfloat16 h2 = __float2bfloat16(v.z), h3 = __float2bfloat16(v.w);
    hv.x = pack2(h0, h1); hv.y = pack2(h2, h3);
    lv.x = pack2(__float2bfloat16(v.x - __bfloat162float(h0)),
                 __float2bfloat16(v.y - __bfloat162float(h1)));
    lv.y = pack2(__float2bfloat16(v.z - __bfloat162float(h2)),
                 __float2bfloat16(v.w - __bfloat162float(h3)));
}

// ---------------- prep kernels (globals referenced ONLY from device code) ---
__global__ void zero_kernel() {
    if (threadIdx.x < NEXP) g_counts[threadIdx.x] = 0;
    if (threadIdx.x == 0) g_aux = 0.f;
}

__global__ void split_x_kernel(const float4* __restrict__ src) {
    size_t i = (size_t)blockIdx.x * blockDim.x + threadIdx.x;
    uint2 hv, lv;
    split4(src[i], hv, lv);
    ((uint2*)g_XH)[i] = hv;
    ((uint2*)g_XL)[i] = lv;
}
__global__ void split_w12_kernel(const float4* __restrict__ src) {
    size_t i = (size_t)blockIdx.x * blockDim.x + threadIdx.x;
    uint2 hv, lv;
    split4(src[i], hv, lv);
    ((uint2*)g_W12H)[i] = hv;
    ((uint2*)g_W12L)[i] = lv;
}
__global__ void split_w3_kernel(const float4* __restrict__ src) {
    size_t i = (size_t)blockIdx.x * blockDim.x + threadIdx.x;
    uint2 hv, lv;
    split4(src[i], hv, lv);
    ((uint2*)g_W3H)[i] = hv;
    ((uint2*)g_W3L)[i] = lv;
}

__global__ void router_kernel(const float* __restrict__ x, const float* __restrict__ rw,
                              const float* __restrict__ rb) {
    __shared__ float4 s_rw[NEXP * DIMD / 4];
    for (int i = threadIdx.x; i < NEXP * DIMD / 4; i += 128) s_rw[i] = ((const float4*)rw)[i];
    __syncthreads();
    const int warp = threadIdx.x >> 5, lane = threadIdx.x & 31;
    const int t = blockIdx.x * 4 + warp;
    const float4* xr = (const float4*)(x + (size_t)t * DIMD);
    float acc[NEXP];
#pragma unroll
    for (int e = 0; e < NEXP; ++e) acc[e] = 0.f;
#pragma unroll
    for (int i = 0; i < 8; ++i) {
        float4 xv = xr[lane + i * 32];
#pragma unroll
        for (int e = 0; e < NEXP; ++e) {
            float4 wv = s_rw[e * 256 + lane + i * 32];
            acc[e] += xv.x * wv.x + xv.y * wv.y + xv.z * wv.z + xv.w * wv.w;
        }
    }
#pragma unroll
    for (int e = 0; e < NEXP; ++e)
#pragma unroll
        for (int off = 16; off > 0; off >>= 1) acc[e] += __shfl_xor_sync(0xFFFFFFFFu, acc[e], off);
    if (lane == 0) {
        float s[NEXP], aux = 0.f;
#pragma unroll
        for (int e = 0; e < NEXP; ++e) {
            float lg = acc[e] + rb[e];
            aux += lg * lg;
            s[e] = 1.f / (1.f + expf(-lg));
        }
        atomicAdd(&g_aux, aux);
        int idx[TOPK]; float sc[TOPK]; bool used[NEXP];
#pragma unroll
        for (int e = 0; e < NEXP; ++e) used[e] = false;
#pragma unroll
        for (int k = 0; k < TOPK; ++k) {
            int best = 0; float bv = -1e30f;
#pragma unroll
            for (int e = 0; e < NEXP; ++e)
                if (!used[e] && s[e] > bv) { bv = s[e]; best = e; }
            used[best] = true; idx[k] = best; sc[k] = bv;
        }
        float tot = sc[0] + sc[1] + sc[2] + 1e-6f;
#pragma unroll
        for (int k = 0; k < TOPK; ++k) {
            int e = idx[k];
            int pos = atomicAdd(&g_counts[e], 1);
            g_rows[e * NTOK + pos] = t;
            g_tok_e[t * TOPK + k] = e;
            g_tok_pos[t * TOPK + k] = pos;
            g_tok_w[t * TOPK + k] = sc[k] / tot;
        }
    }
}

__global__ void prefix_kernel() {
    int s = 0;
    for (int e = 0; e < NEXP; ++e) { g_offs[e] = s; s += g_counts[e]; }
}

// ---------------- GEMM1: hidden = silu(x@W1) * (x@W2) -----------------------
// CTA: 64 rows x 128 cols of W1 AND 128 cols of W2; K chunks of 32; 3 segments.
#define G1_STG 21504
#define NCH1 96

__global__ __launch_bounds__(256, 2) void gemm1_kernel() {
    __shared__ __align__(128) char smem[2 * G1_STG + 512];
    const int e = blockIdx.z;
    const int ne = g_counts[e];
    const int mtile = blockIdx.x;
    if (mtile * 64 >= ne) return;
    const int ntile = blockIdx.y;
    const int tid = threadIdx.x, wid = tid >> 5, lane = tid & 31;

    int* rows_s = (int*)(smem + 2 * G1_STG);
    const uint32_t sbase = smem_u32(smem);
    if (tid < 64) {
        int lr = mtile * 64 + tid;
        rows_s[tid] = (lr < ne) ? g_rows[e * NTOK + lr] : 0;
    }
    __syncthreads();

    const size_t wb = (size_t)e * DIMD * 2 * HID;

    auto issue = [&](int c) {
        const int seg = c >> 5, k0 = (c & 31) * 32;
        const __nv_bfloat16* As = (seg == 2) ? g_XL : g_XH;
        const __nv_bfloat16* Bs = ((seg == 1) ? g_W12L : g_W12H) + wb;
        const uint32_t bufA = sbase + (c & 1) * G1_STG;
        const uint32_t bufB = bufA + 5120;
        {   // A: 64 rows x 64 bytes
            int row = tid >> 2, c4 = tid & 3;
            const char* g = (const char*)(As + (size_t)rows_s[row] * DIMD + k0) + c4 * 16;
            cpa16(bufA + row * 80 + c4 * 16, g);
        }
#pragma unroll
        for (int j = 0; j < 4; ++j) {  // B: 2 halves x 32 k-rows x 256B
            int i = tid + j * 256;
            int b = i >> 9, r = (i >> 4) & 31, cc = i & 15;
            const char* g = (const char*)(Bs + (size_t)(k0 + r) * (2 * HID) +
                                          b * HID + ntile * 128 + cc * 8);
            cpa16(bufB + b * 8192 + r * 256 + ((cc ^ (r & 7)) << 4), g);
        }
    };

    const int mw = wid >> 2, nw = wid & 3;
    const int m0 = mw * 32, n0 = nw * 32;
    float acc1[2][4][4], acc2[2][4][4];
#pragma unroll
    for (int a = 0; a < 2; ++a)
#pragma unroll
        for (int b = 0; b < 4; ++b)
#pragma unroll
            for (int r = 0; r < 4; ++r) { acc1[a][b][r] = 0.f; acc2[a][b][r] = 0.f; }

    issue(0); cp_commit();

    for (int c = 0; c < NCH1; ++c) {
        if (c + 1 < NCH1) issue(c + 1);
        cp_commit();
        cp_wait1();
        __syncthreads();
        const uint32_t bufA = sbase + (c & 1) * G1_STG;
        const uint32_t bufB = bufA + 5120;
#pragma unroll
        for (int ks = 0; ks < 32; ks += 16) {
            uint32_t af[2][4];
#pragma unroll
            for (int mi = 0; mi < 2; ++mi)
                ldsm4(af[mi], bufA + (m0 + mi * 16 + (lane & 15)) * 80 + ks * 2 + (lane >> 4) * 16);
            uint32_t bf1[2][4], bf2[2][4];
            const int grp = lane >> 3;
            const int kr = ks + ((grp & 1) << 3) + (lane & 7);
#pragma unroll
            for (int gj = 0; gj < 2; ++gj) {
                int cc = ((n0 + (gj << 4)) >> 3) + (grp >> 1);
                uint32_t a1 = bufB + kr * 256 + ((cc ^ (kr & 7)) << 4);
                ldsm4t(bf1[gj], a1);
                ldsm4t(bf2[gj], a1 + 8192);
            }
#pragma unroll
            for (int mi = 0; mi < 2; ++mi)
#pragma unroll
                for (int nj = 0; nj < 4; ++nj) {
                    mma16816(acc1[mi][nj], af[mi], &bf1[nj >> 1][(nj & 1) * 2]);
                    mma16816(acc2[mi][nj], af[mi], &bf2[nj >> 1][(nj & 1) * 2]);
                }
        }
        __syncthreads();
    }

    // epilogue: h = silu(a1) * a2 -> bf16 hi/lo
    const int rowbase = g_offs[e];
#pragma unroll
    for (int mi = 0; mi < 2; ++mi)
#pragma unroll
        for (int h = 0; h < 2; ++h) {
            int rl = m0 + mi * 16 + h * 8 + (lane >> 2);
            int lr = mtile * 64 + rl;
            if (lr < ne) {
                size_t rowb = (size_t)(rowbase + lr) * HID + ntile * 128;
#pragma unroll
                for (int nj = 0; nj < 4; ++nj) {
                    float a1a = acc1[mi][nj][h * 2], a1b = acc1[mi][nj][h * 2 + 1];
                    float a2a = acc2[mi][nj][h * 2], a2b = acc2[mi][nj][h * 2 + 1];
                    float ha = a1a / (1.f + expf(-a1a)) * a2a;
                    float hb = a1b / (1.f + expf(-a1b)) * a2b;
                    __nv_bfloat16 hha = __float2bfloat16(ha), hhb = __float2bfloat16(hb);
                    __nv_bfloat16 hla = __float2bfloat16(ha - __bfloat162float(hha));
                    __nv_bfloat16 hlb = __float2bfloat16(hb - __bfloat162float(hhb));
                    int col = n0 + nj * 8 + 2 * (lane & 3);
                    *(uint32_t*)&g_HIDH[rowb + col] = pack2(hha, hhb);
                    *(uint32_t*)&g_HIDL[rowb + col] = pack2(hla, hlb);
                }
            }
        }
}

// ---------------- GEMM2: out_part = hidden @ W3 -----------------------------
#define G2_STG 13312
#define NCH2 384

__global__ __launch_bounds__(256, 2) void gemm2_kernel() {
    __shared__ __align__(128) char smem[3 * G2_STG];
    const int e = blockIdx.z;
    const int ne = g_counts[e];
    const int mtile = blockIdx.x;
    if (mtile * 64 >= ne) return;
    const int ntile = blockIdx.y;
    const int tid = threadIdx.x, wid = tid >> 5, lane = tid & 31;

    const uint32_t sbase = smem_u32(smem);
    const int row0 = g_offs[e] + mtile * 64;
    const size_t wb = (size_t)e * HID * DIMD;

    auto issue = [&](int c) {
        const int seg = c >> 7, k0 = (c & 127) * 32;
        const __nv_bfloat16* As = (seg == 2) ? g_HIDL : g_HIDH;
        const __nv_bfloat16* Bs = ((seg == 1) ? g_W3L : g_W3H) + wb;
        const int st = c % 3;
        const uint32_t bufA = sbase + st * G2_STG;
        const uint32_t bufB = bufA + 5120;
        {
            int row = tid >> 2, c4 = tid & 3;
            const char* g = (const char*)(As + (size_t)(row0 + row) * HID + k0) + c4 * 16;
            cpa16(bufA + row * 80 + c4 * 16, g);
        }
#pragma unroll
        for (int j = 0; j < 2; ++j) {
            int i = tid + j * 256;
            int r = (i >> 4) & 31, cc = i & 15;
            const char* g = (const char*)(Bs + (size_t)(k0 + r) * DIMD + ntile * 128 + cc * 8);
            cpa16(bufB + r * 256 + ((cc ^ (r & 7)) << 4), g);
        }
    };

    const int mw = wid >> 2, nw = wid & 3;
    const int m0 = mw * 32, n0 = nw * 32;
    float acc[2][4][4];
#pragma unroll
    for (int a = 0; a < 2; ++a)
#pragma unroll
        for (int b = 0; b < 4; ++b)
#pragma unroll
            for (int r = 0; r < 4; ++r) acc[a][b][r] = 0.f;

    issue(0); cp_commit();
    issue(1); cp_commit();

    for (int c = 0; c < NCH2; ++c) {
        if (c + 2 < NCH2) issue(c + 2);
        cp_commit();
        cp_wait2();
        __syncthreads();
        const int st = c % 3;
        const uint32_t bufA = sbase + st * G2_STG;
        const uint32_t bufB = bufA + 5120;
#pragma unroll
        for (int ks = 0; ks < 32; ks += 16) {
            uint32_t af[2][4];
#pragma unroll
            for (int mi = 0; mi < 2; ++mi)
                ldsm4(af[mi], bufA + (m0 + mi * 16 + (lane & 15)) * 80 + ks * 2 + (lane >> 4) * 16);
            uint32_t bf[2][4];
            const int grp = lane >> 3;
            const int kr = ks + ((grp & 1) << 3) + (lane & 7);
#pragma unroll
            for (int gj = 0; gj < 2; ++gj) {
                int cc = ((n0 + (gj << 4)) >> 3) + (grp >> 1);
                ldsm4t(bf[gj], bufB + kr * 256 + ((cc ^ (kr & 7)) << 4));
            }
#pragma unroll
            for (int mi = 0; mi < 2; ++mi)
#pragma unroll
                for (int nj = 0; nj < 4; ++nj)
                    mma16816(acc[mi][nj], af[mi], &bf[nj >> 1][(nj & 1) * 2]);
        }
        __syncthreads();
    }

#pragma unroll
    for (int mi = 0; mi < 2; ++mi)
#pragma unroll
        for (int h = 0; h < 2; ++h) {
            int rl = m0 + mi * 16 + h * 8 + (lane >> 2);
            int lr = mtile * 64 + rl;
            if (lr < ne) {
                size_t rowb = (size_t)(row0 + rl) * DIMD + ntile * 128;
#pragma unroll
                for (int nj = 0; nj < 4; ++nj) {
                    int col = n0 + nj * 8 + 2 * (lane & 3);
                    float2 v = make_float2(acc[mi][nj][h * 2], acc[mi][nj][h * 2 + 1]);
                    *(float2*)&g_OUTP[rowb + col] = v;
                }
            }
        }
}

// ---------------- combine ---------------------------------------------------
__global__ void combine_kernel(float* __restrict__ out, int out_size) {
    const int t = blockIdx.x, tid = threadIdx.x;
    float4 acc = make_float4(0.f, 0.f, 0.f, 0.f);
#pragma unroll
    for (int k = 0; k < TOPK; ++k) {
        int e = g_tok_e[t * TOPK + k];
        int row = g_offs[e] + g_tok_pos[t * TOPK + k];
        float w = g_tok_w[t * TOPK + k];
        float4 v = ((const float4*)(g_OUTP + (size_t)row * DIMD))[tid];
        acc.x += w * v.x; acc.y += w * v.y; acc.z += w * v.z; acc.w += w * v.w;
    }
    ((float4*)(out + (size_t)t * DIMD))[tid] = acc;
    if (t == 0 && tid == 0 && out_size > NTOK * DIMD)
        out[NTOK * DIMD] = 0.01f * g_aux / (float)(NTOK * NEXP);
}

// ---------------- launch -----------------------------------------------------
extern "C" void kernel_launch(void* const* d_in, const int* in_sizes, int n_in,
                              void* d_out, int out_size) {
    // Bind inputs by element count (order-proof; all five sizes distinct).
    const float *x = 0, *rw = 0, *rb = 0, *w12 = 0, *w3 = 0;
    for (int i = 0; i < n_in; ++i) {
        switch (in_sizes[i]) {
            case 4194304:  x   = (const float*)d_in[i]; break;  // 2*2048*1024
            case 8192:     rw  = (const float*)d_in[i]; break;  // 8*1024
            case 8:        rb  = (const float*)d_in[i]; break;  // 8
            case 67108864: w12 = (const float*)d_in[i]; break;  // 8*1024*8192
            case 33554432: w3  = (const float*)d_in[i]; break;  // 8*4096*1024
        }
    }
    if (!x || !rw || !rb || !w12 || !w3) {  // positional fallback
        x = (const float*)d_in[0]; rw = (const float*)d_in[1]; rb = (const float*)d_in[2];
        w12 = (const float*)d_in[3]; w3 = (const float*)d_in[4];
    }
    float* out = (float*)d_out;

    zero_kernel<<<1, 32>>>();
    split_x_kernel<<<4096, 256>>>((const float4*)x);
    split_w12_kernel<<<65536, 256>>>((const float4*)w12);
    split_w3_kernel<<<32768, 256>>>((const float4*)w3);
    router_kernel<<<NTOK / 4, 128>>>(x, rw, rb);
    prefix_kernel<<<1, 1>>>();
    gemm1_kernel<<<dim3(64, 32, NEXP), 256>>>();
    gemm2_kernel<<<dim3(64, 8, NEXP), 256>>>();
    combine_kernel<<<NTOK, 256>>>(out, out_size);
}

// round 7
// speedup vs baseline: 1.4262x; 1.4262x over previous
#include <cuda_runtime.h>
#include <cuda_bf16.h>
#include <cstdint>
#include <cstddef>
#include <math.h>

#define DIMD 1024
#define HID  4096
#define NEXP 8
#define TOPK 3
#define NTOK 4096
#define MAXROWS (NTOK * TOPK + 512)

// ---------------- device scratch (allocations forbidden) --------------------
__device__ __nv_bfloat16 g_XH[(size_t)NTOK * DIMD];
__device__ __nv_bfloat16 g_XL[(size_t)NTOK * DIMD];
__device__ __nv_bfloat16 g_W12H[(size_t)NEXP * DIMD * 2 * HID];
__device__ __nv_bfloat16 g_W12L[(size_t)NEXP * DIMD * 2 * HID];
__device__ __nv_bfloat16 g_W3H[(size_t)NEXP * HID * DIMD];
__device__ __nv_bfloat16 g_W3L[(size_t)NEXP * HID * DIMD];
__device__ __nv_bfloat16 g_HIDH[(size_t)MAXROWS * HID];
__device__ __nv_bfloat16 g_HIDL[(size_t)MAXROWS * HID];
__device__ float g_OUTP[(size_t)MAXROWS * DIMD];
__device__ int   g_counts[NEXP];
__device__ int   g_offs[NEXP];
__device__ int   g_rows[NEXP * NTOK];
__device__ int   g_tok_e[NTOK * TOPK];
__device__ int   g_tok_pos[NTOK * TOPK];
__device__ float g_tok_w[NTOK * TOPK];
__device__ float g_aux;

// ---------------- helpers ---------------------------------------------------
__device__ __forceinline__ uint32_t smem_u32(const void* p) {
    uint32_t a;
    asm("{ .reg .u64 t; cvta.to.shared.u64 t, %1; cvt.u32.u64 %0, t; }" : "=r"(a) : "l"(p));
    return a;
}
__device__ __forceinline__ void cpa16(uint32_t s, const void* g) {
    asm volatile("cp.async.cg.shared.global [%0], [%1], 16;" :: "r"(s), "l"(g));
}
__device__ __forceinline__ void cp_commit() {
    asm volatile("cp.async.commit_group;" ::: "memory");
}
__device__ __forceinline__ void cp_wait2() {
    asm volatile("cp.async.wait_group 2;" ::: "memory");
}
__device__ __forceinline__ void ldsm4(uint32_t* r, uint32_t a) {
    asm volatile("ldmatrix.sync.aligned.m8n8.x4.shared.b16 {%0,%1,%2,%3}, [%4];"
                 : "=r"(r[0]), "=r"(r[1]), "=r"(r[2]), "=r"(r[3]) : "r"(a));
}
__device__ __forceinline__ void ldsm4t(uint32_t* r, uint32_t a) {
    asm volatile("ldmatrix.sync.aligned.m8n8.x4.trans.shared.b16 {%0,%1,%2,%3}, [%4];"
                 : "=r"(r[0]), "=r"(r[1]), "=r"(r[2]), "=r"(r[3]) : "r"(a));
}
__device__ __forceinline__ void mma16816(float* c, const uint32_t* a, const uint32_t* b) {
    asm volatile("mma.sync.aligned.m16n8k16.row.col.f32.bf16.bf16.f32 "
                 "{%0,%1,%2,%3}, {%4,%5,%6,%7}, {%8,%9}, {%0,%1,%2,%3};"
                 : "+f"(c[0]), "+f"(c[1]), "+f"(c[2]), "+f"(c[3])
                 : "r"(a[0]), "r"(a[1]), "r"(a[2]), "r"(a[3]), "r"(b[0]), "r"(b[1]));
}
__device__ __forceinline__ uint32_t pack2(__nv_bfloat16 a, __nv_bfloat16 b) {
    return (uint32_t)__bfloat16_as_ushort(a) | ((uint32_t)__bfloat16_as_ushort(b) << 16);
}
__device__ __forceinline__ void split4(float4 v, uint2& hv, uint2& lv) {
    __nv_bfloat16 h0 = __float2bfloat16(v.x), h1 = __float2bfloat16(v.y);
    __nv_bfloat16 h2 = __float2bfloat16(v.z), h3 = __float2bfloat16(v.w);
    hv.x = pack2(h0, h1); hv.y = pack2(h2, h3);
    lv.x = pack2(__float2bfloat16(v.x - __bfloat162float(h0)),
                 __float2bfloat16(v.y - __bfloat162float(h1)));
    lv.y = pack2(__float2bfloat16(v.z - __bfloat162float(h2)),
                 __float2bfloat16(v.w - __bfloat162float(h3)));
}

// ---------------- prep kernels (globals referenced ONLY from device code) ---
__global__ void zero_kernel() {
    if (threadIdx.x < NEXP) g_counts[threadIdx.x] = 0;
    if (threadIdx.x == 0) g_aux = 0.f;
}

__global__ void split_x_kernel(const float4* __restrict__ src) {
    size_t i = (size_t)blockIdx.x * blockDim.x + threadIdx.x;
    uint2 hv, lv;
    split4(src[i], hv, lv);
    ((uint2*)g_XH)[i] = hv;
    ((uint2*)g_XL)[i] = lv;
}
__global__ void split_w12_kernel(const float4* __restrict__ src) {
    size_t i = (size_t)blockIdx.x * blockDim.x + threadIdx.x;
    uint2 hv, lv;
    split4(src[i], hv, lv);
    ((uint2*)g_W12H)[i] = hv;
    ((uint2*)g_W12L)[i] = lv;
}
__global__ void split_w3_kernel(const float4* __restrict__ src) {
    size_t i = (size_t)blockIdx.x * blockDim.x + threadIdx.x;
    uint2 hv, lv;
    split4(src[i], hv, lv);
    ((uint2*)g_W3H)[i] = hv;
    ((uint2*)g_W3L)[i] = lv;
}

__global__ void router_kernel(const float* __restrict__ x, const float* __restrict__ rw,
                              const float* __restrict__ rb) {
    __shared__ float4 s_rw[NEXP * DIMD / 4];
    for (int i = threadIdx.x; i < NEXP * DIMD / 4; i += 128) s_rw[i] = ((const float4*)rw)[i];
    __syncthreads();
    const int warp = threadIdx.x >> 5, lane = threadIdx.x & 31;
    const int t = blockIdx.x * 4 + warp;
    const float4* xr = (const float4*)(x + (size_t)t * DIMD);
    float acc[NEXP];
#pragma unroll
    for (int e = 0; e < NEXP; ++e) acc[e] = 0.f;
#pragma unroll
    for (int i = 0; i < 8; ++i) {
        float4 xv = xr[lane + i * 32];
#pragma unroll
        for (int e = 0; e < NEXP; ++e) {
            float4 wv = s_rw[e * 256 + lane + i * 32];
            acc[e] += xv.x * wv.x + xv.y * wv.y + xv.z * wv.z + xv.w * wv.w;
        }
    }
#pragma unroll
    for (int e = 0; e < NEXP; ++e)
#pragma unroll
        for (int off = 16; off > 0; off >>= 1) acc[e] += __shfl_xor_sync(0xFFFFFFFFu, acc[e], off);
    if (lane == 0) {
        float s[NEXP], aux = 0.f;
#pragma unroll
        for (int e = 0; e < NEXP; ++e) {
            float lg = acc[e] + rb[e];
            aux += lg * lg;
            s[e] = 1.f / (1.f + expf(-lg));
        }
        atomicAdd(&g_aux, aux);
        int idx[TOPK]; float sc[TOPK]; bool used[NEXP];
#pragma unroll
        for (int e = 0; e < NEXP; ++e) used[e] = false;
#pragma unroll
        for (int k = 0; k < TOPK; ++k) {
            int best = 0; float bv = -1e30f;
#pragma unroll
            for (int e = 0; e < NEXP; ++e)
                if (!used[e] && s[e] > bv) { bv = s[e]; best = e; }
            used[best] = true; idx[k] = best; sc[k] = bv;
        }
        float tot = sc[0] + sc[1] + sc[2] + 1e-6f;
#pragma unroll
        for (int k = 0; k < TOPK; ++k) {
            int e = idx[k];
            int pos = atomicAdd(&g_counts[e], 1);
            g_rows[e * NTOK + pos] = t;
            g_tok_e[t * TOPK + k] = e;
            g_tok_pos[t * TOPK + k] = pos;
            g_tok_w[t * TOPK + k] = sc[k] / tot;
        }
    }
}

__global__ void prefix_kernel() {
    int s = 0;
    for (int e = 0; e < NEXP; ++e) { g_offs[e] = s; s += g_counts[e]; }
}

// ---------------- GEMM1: hidden = silu(x@W1) * (x@W2) -----------------------
// CTA: 64 rows x (128 W1-cols + 128 W2-cols). Merged precision segments:
// per 32-K chunk stage Ah,Al + W1h,W2h,W1l,W2l and run 3 MMA combos.
// Stage = 2*5120 (A) + 4*8192 (B) = 43008 B; 3 stages dynamic.
#define G1_STG 43008
#define G1_DYN (3 * G1_STG + 512)
#define NCH1 32

__global__ __launch_bounds__(256, 1) void gemm1_kernel() {
    extern __shared__ __align__(128) char smem[];
    const int e = blockIdx.z;
    const int ne = g_counts[e];
    const int mtile = blockIdx.x;
    if (mtile * 64 >= ne) return;
    const int ntile = blockIdx.y;
    const int tid = threadIdx.x, wid = tid >> 5, lane = tid & 31;

    int* rows_s = (int*)(smem + 3 * G1_STG);
    const uint32_t sbase = smem_u32(smem);
    if (tid < 64) {
        int lr = mtile * 64 + tid;
        rows_s[tid] = (lr < ne) ? g_rows[e * NTOK + lr] : 0;
    }
    __syncthreads();

    const size_t wb = (size_t)e * DIMD * 2 * HID;

    auto issue = [&](int c) {
        const int k0 = c * 32;
        const uint32_t bufAh = sbase + (c % 3) * G1_STG;
        const uint32_t bufAl = bufAh + 5120;
        const uint32_t bufB  = bufAh + 10240;
        {   // A hi+lo: 64 rows x 64 B each
            int row = tid >> 2, c4 = tid & 3;
            size_t off = (size_t)rows_s[row] * DIMD + k0;
            cpa16(bufAh + row * 80 + c4 * 16, (const char*)(g_XH + off) + c4 * 16);
            cpa16(bufAl + row * 80 + c4 * 16, (const char*)(g_XL + off) + c4 * 16);
        }
#pragma unroll
        for (int j = 0; j < 8; ++j) {  // B: mats {W1h,W2h,W1l,W2l} x 32 k-rows x 256B
            int i = tid + j * 256;
            int mat = i >> 9, r = (i >> 4) & 31, cc = i & 15;
            const __nv_bfloat16* Bsrc = (mat >= 2 ? g_W12L : g_W12H) + wb;
            const char* g = (const char*)(Bsrc + (size_t)(k0 + r) * (2 * HID) +
                                          (mat & 1) * HID + ntile * 128 + cc * 8);
            cpa16(bufB + mat * 8192 + r * 256 + ((cc ^ (r & 7)) << 4), g);
        }
    };

    const int mw = wid >> 2, nw = wid & 3;
    const int m0 = mw * 32, n0 = nw * 32;
    float acc1[2][4][4], acc2[2][4][4];
#pragma unroll
    for (int a = 0; a < 2; ++a)
#pragma unroll
        for (int b = 0; b < 4; ++b)
#pragma unroll
            for (int r = 0; r < 4; ++r) { acc1[a][b][r] = 0.f; acc2[a][b][r] = 0.f; }

    issue(0); cp_commit();
    issue(1); cp_commit();

    for (int c = 0; c < NCH1; ++c) {
        if (c + 2 < NCH1) issue(c + 2);
        cp_commit();
        cp_wait2();
        __syncthreads();
        const uint32_t bufAh = sbase + (c % 3) * G1_STG;
        const uint32_t bufAl = bufAh + 5120;
        const uint32_t bufB  = bufAh + 10240;
#pragma unroll
        for (int ks = 0; ks < 32; ks += 16) {
            uint32_t ah[2][4], al[2][4];
#pragma unroll
            for (int mi = 0; mi < 2; ++mi) {
                uint32_t aoff = (m0 + mi * 16 + (lane & 15)) * 80 + ks * 2 + (lane >> 4) * 16;
                ldsm4(ah[mi], bufAh + aoff);
                ldsm4(al[mi], bufAl + aoff);
            }
            uint32_t b1h[2][4], b2h[2][4], b1l[2][4], b2l[2][4];
            const int grp = lane >> 3;
            const int kr = ks + ((grp & 1) << 3) + (lane & 7);
#pragma unroll
            for (int gj = 0; gj < 2; ++gj) {
                int cc = ((n0 + (gj << 4)) >> 3) + (grp >> 1);
                uint32_t off = kr * 256 + ((cc ^ (kr & 7)) << 4);
                ldsm4t(b1h[gj], bufB + off);
                ldsm4t(b2h[gj], bufB + 8192 + off);
                ldsm4t(b1l[gj], bufB + 16384 + off);
                ldsm4t(b2l[gj], bufB + 24576 + off);
            }
#pragma unroll
            for (int mi = 0; mi < 2; ++mi)
#pragma unroll
                for (int nj = 0; nj < 4; ++nj) {
                    const uint32_t* p1h = &b1h[nj >> 1][(nj & 1) * 2];
                    const uint32_t* p2h = &b2h[nj >> 1][(nj & 1) * 2];
                    mma16816(acc1[mi][nj], ah[mi], p1h);
                    mma16816(acc2[mi][nj], ah[mi], p2h);
                    mma16816(acc1[mi][nj], al[mi], p1h);
                    mma16816(acc2[mi][nj], al[mi], p2h);
                    mma16816(acc1[mi][nj], ah[mi], &b1l[nj >> 1][(nj & 1) * 2]);
                    mma16816(acc2[mi][nj], ah[mi], &b2l[nj >> 1][(nj & 1) * 2]);
                }
        }
        __syncthreads();
    }

    // epilogue: h = silu(a1) * a2 -> bf16 hi/lo
    const int rowbase = g_offs[e];
#pragma unroll
    for (int mi = 0; mi < 2; ++mi)
#pragma unroll
        for (int h = 0; h < 2; ++h) {
            int rl = m0 + mi * 16 + h * 8 + (lane >> 2);
            int lr = mtile * 64 + rl;
            if (lr < ne) {
                size_t rowb = (size_t)(rowbase + lr) * HID + ntile * 128;
#pragma unroll
                for (int nj = 0; nj < 4; ++nj) {
                    float a1a = acc1[mi][nj][h * 2], a1b = acc1[mi][nj][h * 2 + 1];
                    float a2a = acc2[mi][nj][h * 2], a2b = acc2[mi][nj][h * 2 + 1];
                    float ha = a1a / (1.f + expf(-a1a)) * a2a;
                    float hb = a1b / (1.f + expf(-a1b)) * a2b;
                    __nv_bfloat16 hha = __float2bfloat16(ha), hhb = __float2bfloat16(hb);
                    __nv_bfloat16 hla = __float2bfloat16(ha - __bfloat162float(hha));
                    __nv_bfloat16 hlb = __float2bfloat16(hb - __bfloat162float(hhb));
                    int col = n0 + nj * 8 + 2 * (lane & 3);
                    *(uint32_t*)&g_HIDH[rowb + col] = pack2(hha, hhb);
                    *(uint32_t*)&g_HIDL[rowb + col] = pack2(hla, hlb);
                }
            }
        }
}

// ---------------- GEMM2: out_part = hidden @ W3 -----------------------------
// CTA: 128 rows x 128 cols; merged segments. Stage = 2*10240 + 2*8192 = 36864.
#define G2_STG 36864
#define G2_DYN (3 * G2_STG)
#define NCH2 128

__global__ __launch_bounds__(256, 1) void gemm2_kernel() {
    extern __shared__ __align__(128) char smem[];
    const int e = blockIdx.z;
    const int ne = g_counts[e];
    const int mtile = blockIdx.x;
    if (mtile * 128 >= ne) return;
    const int ntile = blockIdx.y;
    const int tid = threadIdx.x, wid = tid >> 5, lane = tid & 31;

    const uint32_t sbase = smem_u32(smem);
    const int row0 = g_offs[e] + mtile * 128;
    const size_t wb = (size_t)e * HID * DIMD;

    auto issue = [&](int c) {
        const int k0 = c * 32;
        const uint32_t bufAh = sbase + (c % 3) * G2_STG;
        const uint32_t bufAl = bufAh + 10240;
        const uint32_t bufB  = bufAh + 20480;
#pragma unroll
        for (int j = 0; j < 2; ++j) {  // A hi+lo: 128 rows x 64 B
            int i = tid + j * 256;
            int row = i >> 2, c4 = i & 3;
            size_t off = (size_t)(row0 + row) * HID + k0;
            cpa16(bufAh + row * 80 + c4 * 16, (const char*)(g_HIDH + off) + c4 * 16);
            cpa16(bufAl + row * 80 + c4 * 16, (const char*)(g_HIDL + off) + c4 * 16);
        }
#pragma unroll
        for (int j = 0; j < 2; ++j) {  // B hi+lo: 32 k-rows x 256 B
            int i = tid + j * 256;
            int r = (i >> 4) & 31, cc = i & 15;
            size_t off = (size_t)(k0 + r) * DIMD + ntile * 128 + cc * 8;
            uint32_t dst = r * 256 + ((cc ^ (r & 7)) << 4);
            cpa16(bufB + dst, (const char*)(g_W3H + wb + off));
            cpa16(bufB + 8192 + dst, (const char*)(g_W3L + wb + off));
        }
    };

    const int mw = wid >> 2, nw = wid & 3;
    const int m0 = mw * 64, n0 = nw * 32;
    float acc[4][4][4];
#pragma unroll
    for (int a = 0; a < 4; ++a)
#pragma unroll
        for (int b = 0; b < 4; ++b)
#pragma unroll
            for (int r = 0; r < 4; ++r) acc[a][b][r] = 0.f;

    issue(0); cp_commit();
    issue(1); cp_commit();

    for (int c = 0; c < NCH2; ++c) {
        if (c + 2 < NCH2) issue(c + 2);
        cp_commit();
        cp_wait2();
        __syncthreads();
        const uint32_t bufAh = sbase + (c % 3) * G2_STG;
        const uint32_t bufAl = bufAh + 10240;
        const uint32_t bufB  = bufAh + 20480;
#pragma unroll
        for (int ks = 0; ks < 32; ks += 16) {
            uint32_t ah[4][4], al[4][4];
#pragma unroll
            for (int mi = 0; mi < 4; ++mi) {
                uint32_t aoff = (m0 + mi * 16 + (lane & 15)) * 80 + ks * 2 + (lane >> 4) * 16;
                ldsm4(ah[mi], bufAh + aoff);
                ldsm4(al[mi], bufAl + aoff);
            }
            uint32_t bh[2][4], bl[2][4];
            const int grp = lane >> 3;
            const int kr = ks + ((grp & 1) << 3) + (lane & 7);
#pragma unroll
            for (int gj = 0; gj < 2; ++gj) {
                int cc = ((n0 + (gj << 4)) >> 3) + (grp >> 1);
                uint32_t off = kr * 256 + ((cc ^ (kr & 7)) << 4);
                ldsm4t(bh[gj], bufB + off);
                ldsm4t(bl[gj], bufB + 8192 + off);
            }
#pragma unroll
            for (int mi = 0; mi < 4; ++mi)
#pragma unroll
                for (int nj = 0; nj < 4; ++nj) {
                    const uint32_t* ph = &bh[nj >> 1][(nj & 1) * 2];
                    mma16816(acc[mi][nj], ah[mi], ph);
                    mma16816(acc[mi][nj], al[mi], ph);
                    mma16816(acc[mi][nj], ah[mi], &bl[nj >> 1][(nj & 1) * 2]);
                }
        }
        __syncthreads();
    }

#pragma unroll
    for (int mi = 0; mi < 4; ++mi)
#pragma unroll
        for (int h = 0; h < 2; ++h) {
            int rl = m0 + mi * 16 + h * 8 + (lane >> 2);
            int lr = mtile * 128 + rl;
            if (lr < ne) {
                size_t rowb = (size_t)(row0 + rl) * DIMD + ntile * 128;
#pragma unroll
                for (int nj = 0; nj < 4; ++nj) {
                    int col = n0 + nj * 8 + 2 * (lane & 3);
                    float2 v = make_float2(acc[mi][nj][h * 2], acc[mi][nj][h * 2 + 1]);
                    *(float2*)&g_OUTP[rowb + col] = v;
                }
            }
        }
}

// ---------------- combine ---------------------------------------------------
__global__ void combine_kernel(float* __restrict__ out, int out_size) {
    const int t = blockIdx.x, tid = threadIdx.x;
    float4 acc = make_float4(0.f, 0.f, 0.f, 0.f);
#pragma unroll
    for (int k = 0; k < TOPK; ++k) {
        int e = g_tok_e[t * TOPK + k];
        int row = g_offs[e] + g_tok_pos[t * TOPK + k];
        float w = g_tok_w[t * TOPK + k];
        float4 v = ((const float4*)(g_OUTP + (size_t)row * DIMD))[tid];
        acc.x += w * v.x; acc.y += w * v.y; acc.z += w * v.z; acc.w += w * v.w;
    }
    ((float4*)(out + (size_t)t * DIMD))[tid] = acc;
    if (t == 0 && tid == 0 && out_size > NTOK * DIMD)
        out[NTOK * DIMD] = 0.01f * g_aux / (float)(NTOK * NEXP);
}

// ---------------- launch -----------------------------------------------------
extern "C" void kernel_launch(void* const* d_in, const int* in_sizes, int n_in,
                              void* d_out, int out_size) {
    // Bind inputs by element count (order-proof; all five sizes distinct).
    const float *x = 0, *rw = 0, *rb = 0, *w12 = 0, *w3 = 0;
    for (int i = 0; i < n_in; ++i) {
        switch (in_sizes[i]) {
            case 4194304:  x   = (const float*)d_in[i]; break;  // 2*2048*1024
            case 8192:     rw  = (const float*)d_in[i]; break;  // 8*1024
            case 8:        rb  = (const float*)d_in[i]; break;  // 8
            case 67108864: w12 = (const float*)d_in[i]; break;  // 8*1024*8192
            case 33554432: w3  = (const float*)d_in[i]; break;  // 8*4096*1024
        }
    }
    if (!x || !rw || !rb || !w12 || !w3) {  // positional fallback
        x = (const float*)d_in[0]; rw = (const float*)d_in[1]; rb = (const float*)d_in[2];
        w12 = (const float*)d_in[3]; w3 = (const float*)d_in[4];
    }
    float* out = (float*)d_out;

    cudaFuncSetAttribute(gemm1_kernel, cudaFuncAttributeMaxDynamicSharedMemorySize, G1_DYN);
    cudaFuncSetAttribute(gemm2_kernel, cudaFuncAttributeMaxDynamicSharedMemorySize, G2_DYN);

    zero_kernel<<<1, 32>>>();
    split_x_kernel<<<4096, 256>>>((const float4*)x);
    split_w12_kernel<<<65536, 256>>>((const float4*)w12);
    split_w3_kernel<<<32768, 256>>>((const float4*)w3);
    router_kernel<<<NTOK / 4, 128>>>(x, rw, rb);
    prefix_kernel<<<1, 1>>>();
    gemm1_kernel<<<dim3(64, 32, NEXP), 256, G1_DYN>>>();
    gemm2_kernel<<<dim3(32, 8, NEXP), 256, G2_DYN>>>();
    combine_kernel<<<NTOK, 256>>>(out, out_size);
}

// round 8
// speedup vs baseline: 2.1811x; 1.5293x over previous
#include <cuda_runtime.h>
#include <cuda_fp16.h>
#include <cstdint>
#include <cstddef>
#include <math.h>

#define DIMD 1024
#define HID  4096
#define NEXP 8
#define TOPK 3
#define NTOK 4096
#define MAXROWS (NTOK * TOPK + 512)

// ---------------- device scratch (allocations forbidden) --------------------
__device__ __half g_XH[(size_t)NTOK * DIMD];
__device__ __half g_XL[(size_t)NTOK * DIMD];
__device__ __half g_W12H[(size_t)NEXP * DIMD * 2 * HID];
__device__ __half g_W3H[(size_t)NEXP * HID * DIMD];
__device__ __half g_HIDH[(size_t)MAXROWS * HID];
__device__ __half g_HIDL[(size_t)MAXROWS * HID];
__device__ float g_OUTP[(size_t)MAXROWS * DIMD];
__device__ int   g_counts[NEXP];
__device__ int   g_offs[NEXP];
__device__ int   g_rows[NEXP * NTOK];
__device__ int   g_tok_e[NTOK * TOPK];
__device__ int   g_tok_pos[NTOK * TOPK];
__device__ float g_tok_w[NTOK * TOPK];
__device__ float g_aux;

// ---------------- helpers ---------------------------------------------------
__device__ __forceinline__ uint32_t smem_u32(const void* p) {
    uint32_t a;
    asm("{ .reg .u64 t; cvta.to.shared.u64 t, %1; cvt.u32.u64 %0, t; }" : "=r"(a) : "l"(p));
    return a;
}
__device__ __forceinline__ void cpa16(uint32_t s, const void* g) {
    asm volatile("cp.async.cg.shared.global [%0], [%1], 16;" :: "r"(s), "l"(g));
}
__device__ __forceinline__ void cp_commit() {
    asm volatile("cp.async.commit_group;" ::: "memory");
}
__device__ __forceinline__ void cp_wait2() {
    asm volatile("cp.async.wait_group 2;" ::: "memory");
}
__device__ __forceinline__ void ldsm4(uint32_t* r, uint32_t a) {
    asm volatile("ldmatrix.sync.aligned.m8n8.x4.shared.b16 {%0,%1,%2,%3}, [%4];"
                 : "=r"(r[0]), "=r"(r[1]), "=r"(r[2]), "=r"(r[3]) : "r"(a));
}
__device__ __forceinline__ void ldsm4t(uint32_t* r, uint32_t a) {
    asm volatile("ldmatrix.sync.aligned.m8n8.x4.trans.shared.b16 {%0,%1,%2,%3}, [%4];"
                 : "=r"(r[0]), "=r"(r[1]), "=r"(r[2]), "=r"(r[3]) : "r"(a));
}
__device__ __forceinline__ void mma16816(float* c, const uint32_t* a, const uint32_t* b) {
    asm volatile("mma.sync.aligned.m16n8k16.row.col.f32.f16.f16.f32 "
                 "{%0,%1,%2,%3}, {%4,%5,%6,%7}, {%8,%9}, {%0,%1,%2,%3};"
                 : "+f"(c[0]), "+f"(c[1]), "+f"(c[2]), "+f"(c[3])
                 : "r"(a[0]), "r"(a[1]), "r"(a[2]), "r"(a[3]), "r"(b[0]), "r"(b[1]));
}
__device__ __forceinline__ uint32_t pack2h(__half a, __half b) {
    return (uint32_t)__half_as_ushort(a) | ((uint32_t)__half_as_ushort(b) << 16);
}
__device__ __forceinline__ uint2 tohalf4(float4 v) {
    uint2 r;
    r.x = pack2h(__float2half_rn(v.x), __float2half_rn(v.y));
    r.y = pack2h(__float2half_rn(v.z), __float2half_rn(v.w));
    return r;
}
__device__ __forceinline__ void split4h(float4 v, uint2& hv, uint2& lv) {
    __half h0 = __float2half_rn(v.x), h1 = __float2half_rn(v.y);
    __half h2 = __float2half_rn(v.z), h3 = __float2half_rn(v.w);
    hv.x = pack2h(h0, h1); hv.y = pack2h(h2, h3);
    lv.x = pack2h(__float2half_rn(v.x - __half2float(h0)),
                  __float2half_rn(v.y - __half2float(h1)));
    lv.y = pack2h(__float2half_rn(v.z - __half2float(h2)),
                  __float2half_rn(v.w - __half2float(h3)));
}

// ---------------- fused prep: zero + x-split + w12/w3 convert ----------------
// grid: [0,4096) x-pair, [4096,69632) w12, [69632,102400) w3, 102400 zero
__global__ void prep_kernel(const float4* __restrict__ x, const float4* __restrict__ w12,
                            const float4* __restrict__ w3) {
    const int b = blockIdx.x;
    if (b >= 102400) {
        if (threadIdx.x < NEXP) g_counts[threadIdx.x] = 0;
        if (threadIdx.x == 0) g_aux = 0.f;
        return;
    }
    if (b < 4096) {
        size_t i = (size_t)b * 256 + threadIdx.x;
        uint2 hv, lv;
        split4h(x[i], hv, lv);
        ((uint2*)g_XH)[i] = hv;
        ((uint2*)g_XL)[i] = lv;
    } else if (b < 69632) {
        size_t i = (size_t)(b - 4096) * 256 + threadIdx.x;
        ((uint2*)g_W12H)[i] = tohalf4(w12[i]);
    } else {
        size_t i = (size_t)(b - 69632) * 256 + threadIdx.x;
        ((uint2*)g_W3H)[i] = tohalf4(w3[i]);
    }
}

__global__ void router_kernel(const float* __restrict__ x, const float* __restrict__ rw,
                              const float* __restrict__ rb) {
    __shared__ float4 s_rw[NEXP * DIMD / 4];
    for (int i = threadIdx.x; i < NEXP * DIMD / 4; i += 128) s_rw[i] = ((const float4*)rw)[i];
    __syncthreads();
    const int warp = threadIdx.x >> 5, lane = threadIdx.x & 31;
    const int t = blockIdx.x * 4 + warp;
    const float4* xr = (const float4*)(x + (size_t)t * DIMD);
    float acc[NEXP];
#pragma unroll
    for (int e = 0; e < NEXP; ++e) acc[e] = 0.f;
#pragma unroll
    for (int i = 0; i < 8; ++i) {
        float4 xv = xr[lane + i * 32];
#pragma unroll
        for (int e = 0; e < NEXP; ++e) {
            float4 wv = s_rw[e * 256 + lane + i * 32];
            acc[e] += xv.x * wv.x + xv.y * wv.y + xv.z * wv.z + xv.w * wv.w;
        }
    }
#pragma unroll
    for (int e = 0; e < NEXP; ++e)
#pragma unroll
        for (int off = 16; off > 0; off >>= 1) acc[e] += __shfl_xor_sync(0xFFFFFFFFu, acc[e], off);
    if (lane == 0) {
        float s[NEXP], aux = 0.f;
#pragma unroll
        for (int e = 0; e < NEXP; ++e) {
            float lg = acc[e] + rb[e];
            aux += lg * lg;
            s[e] = 1.f / (1.f + expf(-lg));
        }
        atomicAdd(&g_aux, aux);
        int idx[TOPK]; float sc[TOPK]; bool used[NEXP];
#pragma unroll
        for (int e = 0; e < NEXP; ++e) used[e] = false;
#pragma unroll
        for (int k = 0; k < TOPK; ++k) {
            int best = 0; float bv = -1e30f;
#pragma unroll
            for (int e = 0; e < NEXP; ++e)
                if (!used[e] && s[e] > bv) { bv = s[e]; best = e; }
            used[best] = true; idx[k] = best; sc[k] = bv;
        }
        float tot = sc[0] + sc[1] + sc[2] + 1e-6f;
#pragma unroll
        for (int k = 0; k < TOPK; ++k) {
            int e = idx[k];
            int pos = atomicAdd(&g_counts[e], 1);
            g_rows[e * NTOK + pos] = t;
            g_tok_e[t * TOPK + k] = e;
            g_tok_pos[t * TOPK + k] = pos;
            g_tok_w[t * TOPK + k] = sc[k] / tot;
        }
    }
}

__global__ void prefix_kernel() {
    int s = 0;
    for (int e = 0; e < NEXP; ++e) { g_offs[e] = s; s += g_counts[e]; }
}

// ---------------- GEMM1: hidden = silu(x@W1) * (x@W2) -----------------------
// CTA: 64 rows x (128 W1-cols + 128 W2-cols). A = fp16 pair, W = single fp16.
// Stage = 2*5120 (Ah,Al) + 2*8192 (W1,W2) = 26624 B; 4 stages.
#define G1_STG 26624
#define G1_DYN (4 * G1_STG + 512)
#define NCH1 32

__global__ __launch_bounds__(256, 1) void gemm1_kernel() {
    extern __shared__ __align__(128) char smem[];
    const int e = blockIdx.z;
    const int ne = g_counts[e];
    const int mtile = blockIdx.x;
    if (mtile * 64 >= ne) return;
    const int ntile = blockIdx.y;
    const int tid = threadIdx.x, wid = tid >> 5, lane = tid & 31;

    int* rows_s = (int*)(smem + 4 * G1_STG);
    const uint32_t sbase = smem_u32(smem);
    if (tid < 64) {
        int lr = mtile * 64 + tid;
        rows_s[tid] = (lr < ne) ? g_rows[e * NTOK + lr] : 0;
    }
    __syncthreads();

    const size_t wb = (size_t)e * DIMD * 2 * HID;

    auto issue = [&](int c) {
        const int k0 = c * 32;
        const uint32_t bufAh = sbase + (c & 3) * G1_STG;
        const uint32_t bufAl = bufAh + 5120;
        const uint32_t bufB  = bufAh + 10240;
        {   // A hi+lo: 64 rows x 64 B each
            int row = tid >> 2, c4 = tid & 3;
            size_t off = (size_t)rows_s[row] * DIMD + k0;
            cpa16(bufAh + row * 80 + c4 * 16, (const char*)(g_XH + off) + c4 * 16);
            cpa16(bufAl + row * 80 + c4 * 16, (const char*)(g_XL + off) + c4 * 16);
        }
#pragma unroll
        for (int j = 0; j < 4; ++j) {  // B: mats {W1,W2} x 32 k-rows x 256B
            int i = tid + j * 256;
            int mat = i >> 9, r = (i >> 4) & 31, cc = i & 15;
            const char* g = (const char*)(g_W12H + wb + (size_t)(k0 + r) * (2 * HID) +
                                          mat * HID + ntile * 128 + cc * 8);
            cpa16(bufB + mat * 8192 + r * 256 + ((cc ^ (r & 7)) << 4), g);
        }
    };

    const int mw = wid >> 2, nw = wid & 3;
    const int m0 = mw * 32, n0 = nw * 32;
    float acc1[2][4][4], acc2[2][4][4];
#pragma unroll
    for (int a = 0; a < 2; ++a)
#pragma unroll
        for (int b = 0; b < 4; ++b)
#pragma unroll
            for (int r = 0; r < 4; ++r) { acc1[a][b][r] = 0.f; acc2[a][b][r] = 0.f; }

    issue(0); cp_commit();
    issue(1); cp_commit();

    for (int c = 0; c < NCH1; ++c) {
        if (c + 2 < NCH1) issue(c + 2);
        cp_commit();
        cp_wait2();
        __syncthreads();
        const uint32_t bufAh = sbase + (c & 3) * G1_STG;
        const uint32_t bufAl = bufAh + 5120;
        const uint32_t bufB  = bufAh + 10240;
#pragma unroll
        for (int ks = 0; ks < 32; ks += 16) {
            uint32_t ah[2][4], al[2][4];
#pragma unroll
            for (int mi = 0; mi < 2; ++mi) {
                uint32_t aoff = (m0 + mi * 16 + (lane & 15)) * 80 + ks * 2 + (lane >> 4) * 16;
                ldsm4(ah[mi], bufAh + aoff);
                ldsm4(al[mi], bufAl + aoff);
            }
            uint32_t b1[2][4], b2[2][4];
            const int grp = lane >> 3;
            const int kr = ks + ((grp & 1) << 3) + (lane & 7);
#pragma unroll
            for (int gj = 0; gj < 2; ++gj) {
                int cc = ((n0 + (gj << 4)) >> 3) + (grp >> 1);
                uint32_t off = kr * 256 + ((cc ^ (kr & 7)) << 4);
                ldsm4t(b1[gj], bufB + off);
                ldsm4t(b2[gj], bufB + 8192 + off);
            }
#pragma unroll
            for (int mi = 0; mi < 2; ++mi)
#pragma unroll
                for (int nj = 0; nj < 4; ++nj) {
                    const uint32_t* p1 = &b1[nj >> 1][(nj & 1) * 2];
                    const uint32_t* p2 = &b2[nj >> 1][(nj & 1) * 2];
                    mma16816(acc1[mi][nj], ah[mi], p1);
                    mma16816(acc2[mi][nj], ah[mi], p2);
                    mma16816(acc1[mi][nj], al[mi], p1);
                    mma16816(acc2[mi][nj], al[mi], p2);
                }
        }
    }

    // epilogue: h = silu(a1) * a2 -> fp16 hi/lo
    const int rowbase = g_offs[e];
#pragma unroll
    for (int mi = 0; mi < 2; ++mi)
#pragma unroll
        for (int h = 0; h < 2; ++h) {
            int rl = m0 + mi * 16 + h * 8 + (lane >> 2);
            int lr = mtile * 64 + rl;
            if (lr < ne) {
                size_t rowb = (size_t)(rowbase + lr) * HID + ntile * 128;
#pragma unroll
                for (int nj = 0; nj < 4; ++nj) {
                    float a1a = acc1[mi][nj][h * 2], a1b = acc1[mi][nj][h * 2 + 1];
                    float a2a = acc2[mi][nj][h * 2], a2b = acc2[mi][nj][h * 2 + 1];
                    float ha = a1a / (1.f + expf(-a1a)) * a2a;
                    float hb = a1b / (1.f + expf(-a1b)) * a2b;
                    __half hha = __float2half_rn(ha), hhb = __float2half_rn(hb);
                    __half hla = __float2half_rn(ha - __half2float(hha));
                    __half hlb = __float2half_rn(hb - __half2float(hhb));
                    int col = n0 + nj * 8 + 2 * (lane & 3);
                    *(uint32_t*)&g_HIDH[rowb + col] = pack2h(hha, hhb);
                    *(uint32_t*)&g_HIDL[rowb + col] = pack2h(hla, hlb);
                }
            }
        }
}

// ---------------- GEMM2: out_part = hidden @ W3 -----------------------------
// CTA: 128 rows x 128 cols. A = fp16 pair, W3 = single fp16.
// Stage = 2*10240 + 8192 = 28672; 4 stages.
#define G2_STG 28672
#define G2_DYN (4 * G2_STG)
#define NCH2 128

__global__ __launch_bounds__(256, 1) void gemm2_kernel() {
    extern __shared__ __align__(128) char smem[];
    const int e = blockIdx.z;
    const int ne = g_counts[e];
    const int mtile = blockIdx.x;
    if (mtile * 128 >= ne) return;
    const int ntile = blockIdx.y;
    const int tid = threadIdx.x, wid = tid >> 5, lane = tid & 31;

    const uint32_t sbase = smem_u32(smem);
    const int row0 = g_offs[e] + mtile * 128;
    const size_t wb = (size_t)e * HID * DIMD;

    auto issue = [&](int c) {
        const int k0 = c * 32;
        const uint32_t bufAh = sbase + (c & 3) * G2_STG;
        const uint32_t bufAl = bufAh + 10240;
        const uint32_t bufB  = bufAh + 20480;
#pragma unroll
        for (int j = 0; j < 2; ++j) {  // A hi+lo: 128 rows x 64 B
            int i = tid + j * 256;
            int row = i >> 2, c4 = i & 3;
            size_t off = (size_t)(row0 + row) * HID + k0;
            cpa16(bufAh + row * 80 + c4 * 16, (const char*)(g_HIDH + off) + c4 * 16);
            cpa16(bufAl + row * 80 + c4 * 16, (const char*)(g_HIDL + off) + c4 * 16);
        }
#pragma unroll
        for (int j = 0; j < 2; ++j) {  // B: 32 k-rows x 256 B
            int i = tid + j * 256;
            int r = (i >> 4) & 31, cc = i & 15;
            const char* g = (const char*)(g_W3H + wb + (size_t)(k0 + r) * DIMD +
                                          ntile * 128 + cc * 8);
            cpa16(bufB + r * 256 + ((cc ^ (r & 7)) << 4), g);
        }
    };

    const int mw = wid >> 2, nw = wid & 3;
    const int m0 = mw * 64, n0 = nw * 32;
    float acc[4][4][4];
#pragma unroll
    for (int a = 0; a < 4; ++a)
#pragma unroll
        for (int b = 0; b < 4; ++b)
#pragma unroll
            for (int r = 0; r < 4; ++r) acc[a][b][r] = 0.f;

    issue(0); cp_commit();
    issue(1); cp_commit();

    for (int c = 0; c < NCH2; ++c) {
        if (c + 2 < NCH2) issue(c + 2);
        cp_commit();
        cp_wait2();
        __syncthreads();
        const uint32_t bufAh = sbase + (c & 3) * G2_STG;
        const uint32_t bufAl = bufAh + 10240;
        const uint32_t bufB  = bufAh + 20480;
#pragma unroll
        for (int ks = 0; ks < 32; ks += 16) {
            uint32_t ah[4][4], al[4][4];
#pragma unroll
            for (int mi = 0; mi < 4; ++mi) {
                uint32_t aoff = (m0 + mi * 16 + (lane & 15)) * 80 + ks * 2 + (lane >> 4) * 16;
                ldsm4(ah[mi], bufAh + aoff);
                ldsm4(al[mi], bufAl + aoff);
            }
            uint32_t bh[2][4];
            const int grp = lane >> 3;
            const int kr = ks + ((grp & 1) << 3) + (lane & 7);
#pragma unroll
            for (int gj = 0; gj < 2; ++gj) {
                int cc = ((n0 + (gj << 4)) >> 3) + (grp >> 1);
                ldsm4t(bh[gj], bufB + kr * 256 + ((cc ^ (kr & 7)) << 4));
            }
#pragma unroll
            for (int mi = 0; mi < 4; ++mi)
#pragma unroll
                for (int nj = 0; nj < 4; ++nj) {
                    const uint32_t* ph = &bh[nj >> 1][(nj & 1) * 2];
                    mma16816(acc[mi][nj], ah[mi], ph);
                    mma16816(acc[mi][nj], al[mi], ph);
                }
        }
    }

#pragma unroll
    for (int mi = 0; mi < 4; ++mi)
#pragma unroll
        for (int h = 0; h < 2; ++h) {
            int rl = m0 + mi * 16 + h * 8 + (lane >> 2);
            int lr = mtile * 128 + rl;
            if (lr < ne) {
                size_t rowb = (size_t)(row0 + rl) * DIMD + ntile * 128;
#pragma unroll
                for (int nj = 0; nj < 4; ++nj) {
                    int col = n0 + nj * 8 + 2 * (lane & 3);
                    float2 v = make_float2(acc[mi][nj][h * 2], acc[mi][nj][h * 2 + 1]);
                    *(float2*)&g_OUTP[rowb + col] = v;
                }
            }
        }
}

// ---------------- combine ---------------------------------------------------
__global__ void combine_kernel(float* __restrict__ out, int out_size) {
    const int t = blockIdx.x, tid = threadIdx.x;
    float4 acc = make_float4(0.f, 0.f, 0.f, 0.f);
#pragma unroll
    for (int k = 0; k < TOPK; ++k) {
        int e = g_tok_e[t * TOPK + k];
        int row = g_offs[e] + g_tok_pos[t * TOPK + k];
        float w = g_tok_w[t * TOPK + k];
        float4 v = ((const float4*)(g_OUTP + (size_t)row * DIMD))[tid];
        acc.x += w * v.x; acc.y += w * v.y; acc.z += w * v.z; acc.w += w * v.w;
    }
    ((float4*)(out + (size_t)t * DIMD))[tid] = acc;
    if (t == 0 && tid == 0 && out_size > NTOK * DIMD)
        out[NTOK * DIMD] = 0.01f * g_aux / (float)(NTOK * NEXP);
}

// ---------------- launch -----------------------------------------------------
extern "C" void kernel_launch(void* const* d_in, const int* in_sizes, int n_in,
                              void* d_out, int out_size) {
    // Bind inputs by element count (order-proof; all five sizes distinct).
    const float *x = 0, *rw = 0, *rb = 0, *w12 = 0, *w3 = 0;
    for (int i = 0; i < n_in; ++i) {
        switch (in_sizes[i]) {
            case 4194304:  x   = (const float*)d_in[i]; break;  // 2*2048*1024
            case 8192:     rw  = (const float*)d_in[i]; break;  // 8*1024
            case 8:        rb  = (const float*)d_in[i]; break;  // 8
            case 67108864: w12 = (const float*)d_in[i]; break;  // 8*1024*8192
            case 33554432: w3  = (const float*)d_in[i]; break;  // 8*4096*1024
        }
    }
    if (!x || !rw || !rb || !w12 || !w3) {  // positional fallback
        x = (const float*)d_in[0]; rw = (const float*)d_in[1]; rb = (const float*)d_in[2];
        w12 = (const float*)d_in[3]; w3 = (const float*)d_in[4];
    }
    float* out = (float*)d_out;

    cudaFuncSetAttribute(gemm1_kernel, cudaFuncAttributeMaxDynamicSharedMemorySize, G1_DYN);
    cudaFuncSetAttribute(gemm2_kernel, cudaFuncAttributeMaxDynamicSharedMemorySize, G2_DYN);

    prep_kernel<<<102401, 256>>>((const float4*)x, (const float4*)w12, (const float4*)w3);
    router_kernel<<<NTOK / 4, 128>>>(x, rw, rb);
    prefix_kernel<<<1, 1>>>();
    gemm1_kernel<<<dim3(64, 32, NEXP), 256, G1_DYN>>>();
    gemm2_kernel<<<dim3(32, 8, NEXP), 256, G2_DYN>>>();
    combine_kernel<<<NTOK, 256>>>(out, out_size);
}

// round 9
// speedup vs baseline: 3.1426x; 1.4408x over previous
#include <cuda_runtime.h>
#include <cuda_fp16.h>
#include <cstdint>
#include <cstddef>
#include <math.h>

#define DIMD 1024
#define HID  4096
#define NEXP 8
#define TOPK 3
#define NTOK 4096
#define MAXROWS (NTOK * TOPK + 512)

// ---------------- device scratch (allocations forbidden) --------------------
__device__ __half g_XH[(size_t)NTOK * DIMD];
__device__ __half g_XL[(size_t)NTOK * DIMD];
__device__ __half g_W12H[(size_t)NEXP * DIMD * 2 * HID];
__device__ __half g_W3H[(size_t)NEXP * HID * DIMD];
__device__ __half g_HIDH[(size_t)MAXROWS * HID];
__device__ float g_OUTP[(size_t)MAXROWS * DIMD];
__device__ int   g_counts[NEXP];
__device__ int   g_offs[NEXP];
__device__ int   g_rows[NEXP * NTOK];
__device__ int   g_tok_e[NTOK * TOPK];
__device__ int   g_tok_pos[NTOK * TOPK];
__device__ float g_tok_w[NTOK * TOPK];
__device__ float g_aux;

// ---------------- helpers ---------------------------------------------------
__device__ __forceinline__ uint32_t smem_u32(const void* p) {
    uint32_t a;
    asm("{ .reg .u64 t; cvta.to.shared.u64 t, %1; cvt.u32.u64 %0, t; }" : "=r"(a) : "l"(p));
    return a;
}
__device__ __forceinline__ void cpa16(uint32_t s, const void* g) {
    asm volatile("cp.async.cg.shared.global [%0], [%1], 16;" :: "r"(s), "l"(g));
}
__device__ __forceinline__ void cp_commit() {
    asm volatile("cp.async.commit_group;" ::: "memory");
}
__device__ __forceinline__ void cp_wait2() {
    asm volatile("cp.async.wait_group 2;" ::: "memory");
}
__device__ __forceinline__ void ldsm4(uint32_t* r, uint32_t a) {
    asm volatile("ldmatrix.sync.aligned.m8n8.x4.shared.b16 {%0,%1,%2,%3}, [%4];"
                 : "=r"(r[0]), "=r"(r[1]), "=r"(r[2]), "=r"(r[3]) : "r"(a));
}
__device__ __forceinline__ void ldsm4t(uint32_t* r, uint32_t a) {
    asm volatile("ldmatrix.sync.aligned.m8n8.x4.trans.shared.b16 {%0,%1,%2,%3}, [%4];"
                 : "=r"(r[0]), "=r"(r[1]), "=r"(r[2]), "=r"(r[3]) : "r"(a));
}
__device__ __forceinline__ void mma16816(float* c, const uint32_t* a, const uint32_t* b) {
    asm volatile("mma.sync.aligned.m16n8k16.row.col.f32.f16.f16.f32 "
                 "{%0,%1,%2,%3}, {%4,%5,%6,%7}, {%8,%9}, {%0,%1,%2,%3};"
                 : "+f"(c[0]), "+f"(c[1]), "+f"(c[2]), "+f"(c[3])
                 : "r"(a[0]), "r"(a[1]), "r"(a[2]), "r"(a[3]), "r"(b[0]), "r"(b[1]));
}
__device__ __forceinline__ uint32_t pack2h(__half a, __half b) {
    return (uint32_t)__half_as_ushort(a) | ((uint32_t)__half_as_ushort(b) << 16);
}
__device__ __forceinline__ uint2 tohalf4(float4 v) {
    uint2 r;
    r.x = pack2h(__float2half_rn(v.x), __float2half_rn(v.y));
    r.y = pack2h(__float2half_rn(v.z), __float2half_rn(v.w));
    return r;
}
__device__ __forceinline__ void split4h(float4 v, uint2& hv, uint2& lv) {
    __half h0 = __float2half_rn(v.x), h1 = __float2half_rn(v.y);
    __half h2 = __float2half_rn(v.z), h3 = __float2half_rn(v.w);
    hv.x = pack2h(h0, h1); hv.y = pack2h(h2, h3);
    lv.x = pack2h(__float2half_rn(v.x - __half2float(h0)),
                  __float2half_rn(v.y - __half2float(h1)));
    lv.y = pack2h(__float2half_rn(v.z - __half2float(h2)),
                  __float2half_rn(v.w - __half2float(h3)));
}

// ---------------- fused prep: zero + x-split + w12/w3 convert ----------------
__global__ void prep_kernel(const float4* __restrict__ x, const float4* __restrict__ w12,
                            const float4* __restrict__ w3) {
    const int b = blockIdx.x;
    if (b >= 102400) {
        if (threadIdx.x < NEXP) g_counts[threadIdx.x] = 0;
        if (threadIdx.x == 0) g_aux = 0.f;
        return;
    }
    if (b < 4096) {
        size_t i = (size_t)b * 256 + threadIdx.x;
        uint2 hv, lv;
        split4h(x[i], hv, lv);
        ((uint2*)g_XH)[i] = hv;
        ((uint2*)g_XL)[i] = lv;
    } else if (b < 69632) {
        size_t i = (size_t)(b - 4096) * 256 + threadIdx.x;
        ((uint2*)g_W12H)[i] = tohalf4(w12[i]);
    } else {
        size_t i = (size_t)(b - 69632) * 256 + threadIdx.x;
        ((uint2*)g_W3H)[i] = tohalf4(w3[i]);
    }
}

__global__ void router_kernel(const float* __restrict__ x, const float* __restrict__ rw,
                              const float* __restrict__ rb) {
    __shared__ float4 s_rw[NEXP * DIMD / 4];
    for (int i = threadIdx.x; i < NEXP * DIMD / 4; i += 128) s_rw[i] = ((const float4*)rw)[i];
    __syncthreads();
    const int warp = threadIdx.x >> 5, lane = threadIdx.x & 31;
    const int t = blockIdx.x * 4 + warp;
    const float4* xr = (const float4*)(x + (size_t)t * DIMD);
    float acc[NEXP];
#pragma unroll
    for (int e = 0; e < NEXP; ++e) acc[e] = 0.f;
#pragma unroll
    for (int i = 0; i < 8; ++i) {
        float4 xv = xr[lane + i * 32];
#pragma unroll
        for (int e = 0; e < NEXP; ++e) {
            float4 wv = s_rw[e * 256 + lane + i * 32];
            acc[e] += xv.x * wv.x + xv.y * wv.y + xv.z * wv.z + xv.w * wv.w;
        }
    }
#pragma unroll
    for (int e = 0; e < NEXP; ++e)
#pragma unroll
        for (int off = 16; off > 0; off >>= 1) acc[e] += __shfl_xor_sync(0xFFFFFFFFu, acc[e], off);
    if (lane == 0) {
        float s[NEXP], aux = 0.f;
#pragma unroll
        for (int e = 0; e < NEXP; ++e) {
            float lg = acc[e] + rb[e];
            aux += lg * lg;
            s[e] = 1.f / (1.f + expf(-lg));
        }
        atomicAdd(&g_aux, aux);
        int idx[TOPK]; float sc[TOPK]; bool used[NEXP];
#pragma unroll
        for (int e = 0; e < NEXP; ++e) used[e] = false;
#pragma unroll
        for (int k = 0; k < TOPK; ++k) {
            int best = 0; float bv = -1e30f;
#pragma unroll
            for (int e = 0; e < NEXP; ++e)
                if (!used[e] && s[e] > bv) { bv = s[e]; best = e; }
            used[best] = true; idx[k] = best; sc[k] = bv;
        }
        float tot = sc[0] + sc[1] + sc[2] + 1e-6f;
#pragma unroll
        for (int k = 0; k < TOPK; ++k) {
            int e = idx[k];
            int pos = atomicAdd(&g_counts[e], 1);
            g_rows[e * NTOK + pos] = t;
            g_tok_e[t * TOPK + k] = e;
            g_tok_pos[t * TOPK + k] = pos;
            g_tok_w[t * TOPK + k] = sc[k] / tot;
        }
    }
}

__global__ void prefix_kernel() {
    int s = 0;
    for (int e = 0; e < NEXP; ++e) { g_offs[e] = s; s += g_counts[e]; }
}

// ---------------- GEMM1: hidden = silu(x@W1) * (x@W2) -----------------------
// CTA: 64 rows x (128 W1-cols + 128 W2-cols). A = fp16 pair, W = single fp16.
// Stage = 2*5120 (Ah,Al) + 2*8192 (W1,W2) = 26624 B; 4 stages; occ 2.
#define G1_STG 26624
#define G1_DYN (4 * G1_STG + 512)
#define NCH1 32

__global__ __launch_bounds__(256, 2) void gemm1_kernel() {
    extern __shared__ __align__(128) char smem[];
    const int e = blockIdx.z;
    const int ne = g_counts[e];
    const int mtile = blockIdx.x;
    if (mtile * 64 >= ne) return;
    const int ntile = blockIdx.y;
    const int tid = threadIdx.x, wid = tid >> 5, lane = tid & 31;

    int* rows_s = (int*)(smem + 4 * G1_STG);
    const uint32_t sbase = smem_u32(smem);
    if (tid < 64) {
        int lr = mtile * 64 + tid;
        rows_s[tid] = (lr < ne) ? g_rows[e * NTOK + lr] : 0;
    }
    __syncthreads();

    const size_t wb = (size_t)e * DIMD * 2 * HID;

    auto issue = [&](int c) {
        const int k0 = c * 32;
        const uint32_t bufAh = sbase + (c & 3) * G1_STG;
        const uint32_t bufAl = bufAh + 5120;
        const uint32_t bufB  = bufAh + 10240;
        {   // A hi+lo: 64 rows x 64 B each
            int row = tid >> 2, c4 = tid & 3;
            size_t off = (size_t)rows_s[row] * DIMD + k0;
            cpa16(bufAh + row * 80 + c4 * 16, (const char*)(g_XH + off) + c4 * 16);
            cpa16(bufAl + row * 80 + c4 * 16, (const char*)(g_XL + off) + c4 * 16);
        }
#pragma unroll
        for (int j = 0; j < 4; ++j) {  // B: mats {W1,W2} x 32 k-rows x 256B
            int i = tid + j * 256;
            int mat = i >> 9, r = (i >> 4) & 31, cc = i & 15;
            const char* g = (const char*)(g_W12H + wb + (size_t)(k0 + r) * (2 * HID) +
                                          mat * HID + ntile * 128 + cc * 8);
            cpa16(bufB + mat * 8192 + r * 256 + ((cc ^ (r & 7)) << 4), g);
        }
    };

    const int mw = wid >> 2, nw = wid & 3;
    const int m0 = mw * 32, n0 = nw * 32;
    float acc1[2][4][4], acc2[2][4][4];
#pragma unroll
    for (int a = 0; a < 2; ++a)
#pragma unroll
        for (int b = 0; b < 4; ++b)
#pragma unroll
            for (int r = 0; r < 4; ++r) { acc1[a][b][r] = 0.f; acc2[a][b][r] = 0.f; }

    issue(0); cp_commit();
    issue(1); cp_commit();

    for (int c = 0; c < NCH1; ++c) {
        if (c + 2 < NCH1) issue(c + 2);
        cp_commit();
        cp_wait2();
        __syncthreads();
        const uint32_t bufAh = sbase + (c & 3) * G1_STG;
        const uint32_t bufAl = bufAh + 5120;
        const uint32_t bufB  = bufAh + 10240;
#pragma unroll
        for (int ks = 0; ks < 32; ks += 16) {
            uint32_t ah[2][4], al[2][4];
#pragma unroll
            for (int mi = 0; mi < 2; ++mi) {
                uint32_t aoff = (m0 + mi * 16 + (lane & 15)) * 80 + ks * 2 + (lane >> 4) * 16;
                ldsm4(ah[mi], bufAh + aoff);
                ldsm4(al[mi], bufAl + aoff);
            }
            uint32_t b1[2][4], b2[2][4];
            const int grp = lane >> 3;
            const int kr = ks + ((grp & 1) << 3) + (lane & 7);
#pragma unroll
            for (int gj = 0; gj < 2; ++gj) {
                int cc = ((n0 + (gj << 4)) >> 3) + (grp >> 1);
                uint32_t off = kr * 256 + ((cc ^ (kr & 7)) << 4);
                ldsm4t(b1[gj], bufB + off);
                ldsm4t(b2[gj], bufB + 8192 + off);
            }
#pragma unroll
            for (int mi = 0; mi < 2; ++mi)
#pragma unroll
                for (int nj = 0; nj < 4; ++nj) {
                    const uint32_t* p1 = &b1[nj >> 1][(nj & 1) * 2];
                    const uint32_t* p2 = &b2[nj >> 1][(nj & 1) * 2];
                    mma16816(acc1[mi][nj], ah[mi], p1);
                    mma16816(acc2[mi][nj], ah[mi], p2);
                    mma16816(acc1[mi][nj], al[mi], p1);
                    mma16816(acc2[mi][nj], al[mi], p2);
                }
        }
    }

    // epilogue: h = silu(a1) * a2 -> fp16 hi (single term for GEMM2)
    const int rowbase = g_offs[e];
#pragma unroll
    for (int mi = 0; mi < 2; ++mi)
#pragma unroll
        for (int h = 0; h < 2; ++h) {
            int rl = m0 + mi * 16 + h * 8 + (lane >> 2);
            int lr = mtile * 64 + rl;
            if (lr < ne) {
                size_t rowb = (size_t)(rowbase + lr) * HID + ntile * 128;
#pragma unroll
                for (int nj = 0; nj < 4; ++nj) {
                    float a1a = acc1[mi][nj][h * 2], a1b = acc1[mi][nj][h * 2 + 1];
                    float a2a = acc2[mi][nj][h * 2], a2b = acc2[mi][nj][h * 2 + 1];
                    float ha = a1a / (1.f + expf(-a1a)) * a2a;
                    float hb = a1b / (1.f + expf(-a1b)) * a2b;
                    int col = n0 + nj * 8 + 2 * (lane & 3);
                    *(uint32_t*)&g_HIDH[rowb + col] =
                        pack2h(__float2half_rn(ha), __float2half_rn(hb));
                }
            }
        }
}

// ---------------- GEMM2: out_part = hidden @ W3 (single fp16 term) ----------
// CTA: 128 rows x 128 cols. Stage = 10240 (A) + 8192 (B) = 18432; 4 stages; occ 2.
#define G2_STG 18432
#define G2_DYN (4 * G2_STG)
#define NCH2 128

__global__ __launch_bounds__(256, 2) void gemm2_kernel() {
    extern __shared__ __align__(128) char smem[];
    const int e = blockIdx.z;
    const int ne = g_counts[e];
    const int mtile = blockIdx.x;
    if (mtile * 128 >= ne) return;
    const int ntile = blockIdx.y;
    const int tid = threadIdx.x, wid = tid >> 5, lane = tid & 31;

    const uint32_t sbase = smem_u32(smem);
    const int row0 = g_offs[e] + mtile * 128;
    const size_t wb = (size_t)e * HID * DIMD;

    auto issue = [&](int c) {
        const int k0 = c * 32;
        const uint32_t bufA = sbase + (c & 3) * G2_STG;
        const uint32_t bufB = bufA + 10240;
#pragma unroll
        for (int j = 0; j < 2; ++j) {  // A: 128 rows x 64 B
            int i = tid + j * 256;
            int row = i >> 2, c4 = i & 3;
            size_t off = (size_t)(row0 + row) * HID + k0;
            cpa16(bufA + row * 80 + c4 * 16, (const char*)(g_HIDH + off) + c4 * 16);
        }
#pragma unroll
        for (int j = 0; j < 2; ++j) {  // B: 32 k-rows x 256 B
            int i = tid + j * 256;
            int r = (i >> 4) & 31, cc = i & 15;
            const char* g = (const char*)(g_W3H + wb + (size_t)(k0 + r) * DIMD +
                                          ntile * 128 + cc * 8);
            cpa16(bufB + r * 256 + ((cc ^ (r & 7)) << 4), g);
        }
    };

    const int mw = wid >> 2, nw = wid & 3;
    const int m0 = mw * 64, n0 = nw * 32;
    float acc[4][4][4];
#pragma unroll
    for (int a = 0; a < 4; ++a)
#pragma unroll
        for (int b = 0; b < 4; ++b)
#pragma unroll
            for (int r = 0; r < 4; ++r) acc[a][b][r] = 0.f;

    issue(0); cp_commit();
    issue(1); cp_commit();

    for (int c = 0; c < NCH2; ++c) {
        if (c + 2 < NCH2) issue(c + 2);
        cp_commit();
        cp_wait2();
        __syncthreads();
        const uint32_t bufA = sbase + (c & 3) * G2_STG;
        const uint32_t bufB = bufA + 10240;
#pragma unroll
        for (int ks = 0; ks < 32; ks += 16) {
            uint32_t ah[4][4];
#pragma unroll
            for (int mi = 0; mi < 4; ++mi)
                ldsm4(ah[mi], bufA + (m0 + mi * 16 + (lane & 15)) * 80 + ks * 2 + (lane >> 4) * 16);
            uint32_t bh[2][4];
            const int grp = lane >> 3;
            const int kr = ks + ((grp & 1) << 3) + (lane & 7);
#pragma unroll
            for (int gj = 0; gj < 2; ++gj) {
                int cc = ((n0 + (gj << 4)) >> 3) + (grp >> 1);
                ldsm4t(bh[gj], bufB + kr * 256 + ((cc ^ (kr & 7)) << 4));
            }
#pragma unroll
            for (int mi = 0; mi < 4; ++mi)
#pragma unroll
                for (int nj = 0; nj < 4; ++nj)
                    mma16816(acc[mi][nj], ah[mi], &bh[nj >> 1][(nj & 1) * 2]);
        }
    }

#pragma unroll
    for (int mi = 0; mi < 4; ++mi)
#pragma unroll
        for (int h = 0; h < 2; ++h) {
            int rl = m0 + mi * 16 + h * 8 + (lane >> 2);
            int lr = mtile * 128 + rl;
            if (lr < ne) {
                size_t rowb = (size_t)(row0 + rl) * DIMD + ntile * 128;
#pragma unroll
                for (int nj = 0; nj < 4; ++nj) {
                    int col = n0 + nj * 8 + 2 * (lane & 3);
                    float2 v = make_float2(acc[mi][nj][h * 2], acc[mi][nj][h * 2 + 1]);
                    *(float2*)&g_OUTP[rowb + col] = v;
                }
            }
        }
}

// ---------------- combine ---------------------------------------------------
__global__ void combine_kernel(float* __restrict__ out, int out_size) {
    const int t = blockIdx.x, tid = threadIdx.x;
    float4 acc = make_float4(0.f, 0.f, 0.f, 0.f);
#pragma unroll
    for (int k = 0; k < TOPK; ++k) {
        int e = g_tok_e[t * TOPK + k];
        int row = g_offs[e] + g_tok_pos[t * TOPK + k];
        float w = g_tok_w[t * TOPK + k];
        float4 v = ((const float4*)(g_OUTP + (size_t)row * DIMD))[tid];
        acc.x += w * v.x; acc.y += w * v.y; acc.z += w * v.z; acc.w += w * v.w;
    }
    ((float4*)(out + (size_t)t * DIMD))[tid] = acc;
    if (t == 0 && tid == 0 && out_size > NTOK * DIMD)
        out[NTOK * DIMD] = 0.01f * g_aux / (float)(NTOK * NEXP);
}

// ---------------- launch -----------------------------------------------------
extern "C" void kernel_launch(void* const* d_in, const int* in_sizes, int n_in,
                              void* d_out, int out_size) {
    const float *x = 0, *rw = 0, *rb = 0, *w12 = 0, *w3 = 0;
    for (int i = 0; i < n_in; ++i) {
        switch (in_sizes[i]) {
            case 4194304:  x   = (const float*)d_in[i]; break;
            case 8192:     rw  = (const float*)d_in[i]; break;
            case 8:        rb  = (const float*)d_in[i]; break;
            case 67108864: w12 = (const float*)d_in[i]; break;
            case 33554432: w3  = (const float*)d_in[i]; break;
        }
    }
    if (!x || !rw || !rb || !w12 || !w3) {
        x = (const float*)d_in[0]; rw = (const float*)d_in[1]; rb = (const float*)d_in[2];
        w12 = (const float*)d_in[3]; w3 = (const float*)d_in[4];
    }
    float* out = (float*)d_out;

    cudaFuncSetAttribute(gemm1_kernel, cudaFuncAttributeMaxDynamicSharedMemorySize, G1_DYN);
    cudaFuncSetAttribute(gemm2_kernel, cudaFuncAttributeMaxDynamicSharedMemorySize, G2_DYN);

    prep_kernel<<<102401, 256>>>((const float4*)x, (const float4*)w12, (const float4*)w3);
    router_kernel<<<NTOK / 4, 128>>>(x, rw, rb);
    prefix_kernel<<<1, 1>>>();
    gemm1_kernel<<<dim3(64, 32, NEXP), 256, G1_DYN>>>();
    gemm2_kernel<<<dim3(32, 8, NEXP), 256, G2_DYN>>>();
    combine_kernel<<<NTOK, 256>>>(out, out_size);
}

// round 10
// speedup vs baseline: 4.2700x; 1.3587x over previous
#include <cuda_runtime.h>
#include <cuda_fp16.h>
#include <cstdint>
#include <cstddef>
#include <math.h>

#define DIMD 1024
#define HID  4096
#define NEXP 8
#define TOPK 3
#define NTOK 4096
#define MAXROWS (NTOK * TOPK + 512)

// ---------------- device scratch (allocations forbidden) --------------------
__device__ __half g_XH[(size_t)NTOK * DIMD];
__device__ __half g_W12H[(size_t)NEXP * DIMD * 2 * HID];
__device__ __half g_W3H[(size_t)NEXP * HID * DIMD];
__device__ __half g_HIDH[(size_t)MAXROWS * HID];
__device__ float g_OUTP[(size_t)MAXROWS * DIMD];
__device__ int   g_counts[NEXP];
__device__ int   g_offs[NEXP];
__device__ int   g_rows[NEXP * NTOK];
__device__ int   g_tok_e[NTOK * TOPK];
__device__ int   g_tok_pos[NTOK * TOPK];
__device__ float g_tok_w[NTOK * TOPK];
__device__ float g_aux;

// ---------------- helpers ---------------------------------------------------
__device__ __forceinline__ uint32_t smem_u32(const void* p) {
    uint32_t a;
    asm("{ .reg .u64 t; cvta.to.shared.u64 t, %1; cvt.u32.u64 %0, t; }" : "=r"(a) : "l"(p));
    return a;
}
__device__ __forceinline__ void cpa16(uint32_t s, const void* g) {
    asm volatile("cp.async.cg.shared.global [%0], [%1], 16;" :: "r"(s), "l"(g));
}
__device__ __forceinline__ void cp_commit() {
    asm volatile("cp.async.commit_group;" ::: "memory");
}
__device__ __forceinline__ void cp_wait2() {
    asm volatile("cp.async.wait_group 2;" ::: "memory");
}
__device__ __forceinline__ void ldsm4(uint32_t* r, uint32_t a) {
    asm volatile("ldmatrix.sync.aligned.m8n8.x4.shared.b16 {%0,%1,%2,%3}, [%4];"
                 : "=r"(r[0]), "=r"(r[1]), "=r"(r[2]), "=r"(r[3]) : "r"(a));
}
__device__ __forceinline__ void ldsm4t(uint32_t* r, uint32_t a) {
    asm volatile("ldmatrix.sync.aligned.m8n8.x4.trans.shared.b16 {%0,%1,%2,%3}, [%4];"
                 : "=r"(r[0]), "=r"(r[1]), "=r"(r[2]), "=r"(r[3]) : "r"(a));
}
__device__ __forceinline__ void mma16816(float* c, const uint32_t* a, const uint32_t* b) {
    asm volatile("mma.sync.aligned.m16n8k16.row.col.f32.f16.f16.f32 "
                 "{%0,%1,%2,%3}, {%4,%5,%6,%7}, {%8,%9}, {%0,%1,%2,%3};"
                 : "+f"(c[0]), "+f"(c[1]), "+f"(c[2]), "+f"(c[3])
                 : "r"(a[0]), "r"(a[1]), "r"(a[2]), "r"(a[3]), "r"(b[0]), "r"(b[1]));
}
__device__ __forceinline__ uint32_t pack2h(__half a, __half b) {
    return (uint32_t)__half_as_ushort(a) | ((uint32_t)__half_as_ushort(b) << 16);
}
__device__ __forceinline__ uint2 tohalf4(float4 v) {
    uint2 r;
    r.x = pack2h(__float2half_rn(v.x), __float2half_rn(v.y));
    r.y = pack2h(__float2half_rn(v.z), __float2half_rn(v.w));
    return r;
}

// ---------------- fused prep: zero + x/w12/w3 convert ------------------------
__global__ void prep_kernel(const float4* __restrict__ x, const float4* __restrict__ w12,
                            const float4* __restrict__ w3) {
    const int b = blockIdx.x;
    if (b >= 102400) {
        if (threadIdx.x < NEXP) g_counts[threadIdx.x] = 0;
        if (threadIdx.x == 0) g_aux = 0.f;
        return;
    }
    if (b < 4096) {
        size_t i = (size_t)b * 256 + threadIdx.x;
        ((uint2*)g_XH)[i] = tohalf4(x[i]);
    } else if (b < 69632) {
        size_t i = (size_t)(b - 4096) * 256 + threadIdx.x;
        ((uint2*)g_W12H)[i] = tohalf4(w12[i]);
    } else {
        size_t i = (size_t)(b - 69632) * 256 + threadIdx.x;
        ((uint2*)g_W3H)[i] = tohalf4(w3[i]);
    }
}

__global__ void router_kernel(const float* __restrict__ x, const float* __restrict__ rw,
                              const float* __restrict__ rb) {
    __shared__ float4 s_rw[NEXP * DIMD / 4];
    for (int i = threadIdx.x; i < NEXP * DIMD / 4; i += 128) s_rw[i] = ((const float4*)rw)[i];
    __syncthreads();
    const int warp = threadIdx.x >> 5, lane = threadIdx.x & 31;
    const int t = blockIdx.x * 4 + warp;
    const float4* xr = (const float4*)(x + (size_t)t * DIMD);
    float acc[NEXP];
#pragma unroll
    for (int e = 0; e < NEXP; ++e) acc[e] = 0.f;
#pragma unroll
    for (int i = 0; i < 8; ++i) {
        float4 xv = xr[lane + i * 32];
#pragma unroll
        for (int e = 0; e < NEXP; ++e) {
            float4 wv = s_rw[e * 256 + lane + i * 32];
            acc[e] += xv.x * wv.x + xv.y * wv.y + xv.z * wv.z + xv.w * wv.w;
        }
    }
#pragma unroll
    for (int e = 0; e < NEXP; ++e)
#pragma unroll
        for (int off = 16; off > 0; off >>= 1) acc[e] += __shfl_xor_sync(0xFFFFFFFFu, acc[e], off);
    if (lane == 0) {
        float s[NEXP], aux = 0.f;
#pragma unroll
        for (int e = 0; e < NEXP; ++e) {
            float lg = acc[e] + rb[e];
            aux += lg * lg;
            s[e] = 1.f / (1.f + expf(-lg));
        }
        atomicAdd(&g_aux, aux);
        int idx[TOPK]; float sc[TOPK]; bool used[NEXP];
#pragma unroll
        for (int e = 0; e < NEXP; ++e) used[e] = false;
#pragma unroll
        for (int k = 0; k < TOPK; ++k) {
            int best = 0; float bv = -1e30f;
#pragma unroll
            for (int e = 0; e < NEXP; ++e)
                if (!used[e] && s[e] > bv) { bv = s[e]; best = e; }
            used[best] = true; idx[k] = best; sc[k] = bv;
        }
        float tot = sc[0] + sc[1] + sc[2] + 1e-6f;
#pragma unroll
        for (int k = 0; k < TOPK; ++k) {
            int e = idx[k];
            int pos = atomicAdd(&g_counts[e], 1);
            g_rows[e * NTOK + pos] = t;
            g_tok_e[t * TOPK + k] = e;
            g_tok_pos[t * TOPK + k] = pos;
            g_tok_w[t * TOPK + k] = sc[k] / tot;
        }
    }
}

__global__ void prefix_kernel() {
    int s = 0;
    for (int e = 0; e < NEXP; ++e) { g_offs[e] = s; s += g_counts[e]; }
}

// ---------------- GEMM1: hidden = silu(x@W1) * (x@W2) -----------------------
// CTA: 64 rows x (128 W1-cols + 128 W2-cols). A = single fp16, W = single fp16.
// Stage = 5120 (A) + 2*8192 (W1,W2) = 21504 B; 4 stages; occ 2.
#define G1_STG 21504
#define G1_DYN (4 * G1_STG + 512)
#define NCH1 32

__global__ __launch_bounds__(256, 2) void gemm1_kernel() {
    extern __shared__ __align__(128) char smem[];
    const int e = blockIdx.z;
    const int ne = g_counts[e];
    const int mtile = blockIdx.x;
    if (mtile * 64 >= ne) return;
    const int ntile = blockIdx.y;
    const int tid = threadIdx.x, wid = tid >> 5, lane = tid & 31;

    int* rows_s = (int*)(smem + 4 * G1_STG);
    const uint32_t sbase = smem_u32(smem);
    if (tid < 64) {
        int lr = mtile * 64 + tid;
        rows_s[tid] = (lr < ne) ? g_rows[e * NTOK + lr] : 0;
    }
    __syncthreads();

    const size_t wb = (size_t)e * DIMD * 2 * HID;

    auto issue = [&](int c) {
        const int k0 = c * 32;
        const uint32_t bufA = sbase + (c & 3) * G1_STG;
        const uint32_t bufB = bufA + 5120;
        {   // A: 64 rows x 64 B
            int row = tid >> 2, c4 = tid & 3;
            size_t off = (size_t)rows_s[row] * DIMD + k0;
            cpa16(bufA + row * 80 + c4 * 16, (const char*)(g_XH + off) + c4 * 16);
        }
#pragma unroll
        for (int j = 0; j < 4; ++j) {  // B: mats {W1,W2} x 32 k-rows x 256B
            int i = tid + j * 256;
            int mat = i >> 9, r = (i >> 4) & 31, cc = i & 15;
            const char* g = (const char*)(g_W12H + wb + (size_t)(k0 + r) * (2 * HID) +
                                          mat * HID + ntile * 128 + cc * 8);
            cpa16(bufB + mat * 8192 + r * 256 + ((cc ^ (r & 7)) << 4), g);
        }
    };

    const int mw = wid >> 2, nw = wid & 3;
    const int m0 = mw * 32, n0 = nw * 32;
    float acc1[2][4][4], acc2[2][4][4];
#pragma unroll
    for (int a = 0; a < 2; ++a)
#pragma unroll
        for (int b = 0; b < 4; ++b)
#pragma unroll
            for (int r = 0; r < 4; ++r) { acc1[a][b][r] = 0.f; acc2[a][b][r] = 0.f; }

    issue(0); cp_commit();
    issue(1); cp_commit();

    for (int c = 0; c < NCH1; ++c) {
        if (c + 2 < NCH1) issue(c + 2);
        cp_commit();
        cp_wait2();
        __syncthreads();
        const uint32_t bufA = sbase + (c & 3) * G1_STG;
        const uint32_t bufB = bufA + 5120;
#pragma unroll
        for (int ks = 0; ks < 32; ks += 16) {
            uint32_t ah[2][4];
#pragma unroll
            for (int mi = 0; mi < 2; ++mi)
                ldsm4(ah[mi], bufA + (m0 + mi * 16 + (lane & 15)) * 80 + ks * 2 + (lane >> 4) * 16);
            uint32_t b1[2][4], b2[2][4];
            const int grp = lane >> 3;
            const int kr = ks + ((grp & 1) << 3) + (lane & 7);
#pragma unroll
            for (int gj = 0; gj < 2; ++gj) {
                int cc = ((n0 + (gj << 4)) >> 3) + (grp >> 1);
                uint32_t off = kr * 256 + ((cc ^ (kr & 7)) << 4);
                ldsm4t(b1[gj], bufB + off);
                ldsm4t(b2[gj], bufB + 8192 + off);
            }
#pragma unroll
            for (int mi = 0; mi < 2; ++mi)
#pragma unroll
                for (int nj = 0; nj < 4; ++nj) {
                    mma16816(acc1[mi][nj], ah[mi], &b1[nj >> 1][(nj & 1) * 2]);
                    mma16816(acc2[mi][nj], ah[mi], &b2[nj >> 1][(nj & 1) * 2]);
                }
        }
    }

    // epilogue: h = silu(a1) * a2 -> fp16
    const int rowbase = g_offs[e];
#pragma unroll
    for (int mi = 0; mi < 2; ++mi)
#pragma unroll
        for (int h = 0; h < 2; ++h) {
            int rl = m0 + mi * 16 + h * 8 + (lane >> 2);
            int lr = mtile * 64 + rl;
            if (lr < ne) {
                size_t rowb = (size_t)(rowbase + lr) * HID + ntile * 128;
#pragma unroll
                for (int nj = 0; nj < 4; ++nj) {
                    float a1a = acc1[mi][nj][h * 2], a1b = acc1[mi][nj][h * 2 + 1];
                    float a2a = acc2[mi][nj][h * 2], a2b = acc2[mi][nj][h * 2 + 1];
                    float ha = a1a / (1.f + expf(-a1a)) * a2a;
                    float hb = a1b / (1.f + expf(-a1b)) * a2b;
                    int col = n0 + nj * 8 + 2 * (lane & 3);
                    *(uint32_t*)&g_HIDH[rowb + col] =
                        pack2h(__float2half_rn(ha), __float2half_rn(hb));
                }
            }
        }
}

// ---------------- GEMM2: out_part = hidden @ W3 (single fp16 term) ----------
// CTA: 128 rows x 128 cols. Stage = 10240 (A) + 8192 (B) = 18432; 4 stages; occ 2.
#define G2_STG 18432
#define G2_DYN (4 * G2_STG)
#define NCH2 128

__global__ __launch_bounds__(256, 2) void gemm2_kernel() {
    extern __shared__ __align__(128) char smem[];
    const int e = blockIdx.z;
    const int ne = g_counts[e];
    const int mtile = blockIdx.x;
    if (mtile * 128 >= ne) return;
    const int ntile = blockIdx.y;
    const int tid = threadIdx.x, wid = tid >> 5, lane = tid & 31;

    const uint32_t sbase = smem_u32(smem);
    const int row0 = g_offs[e] + mtile * 128;
    const size_t wb = (size_t)e * HID * DIMD;

    auto issue = [&](int c) {
        const int k0 = c * 32;
        const uint32_t bufA = sbase + (c & 3) * G2_STG;
        const uint32_t bufB = bufA + 10240;
#pragma unroll
        for (int j = 0; j < 2; ++j) {  // A: 128 rows x 64 B
            int i = tid + j * 256;
            int row = i >> 2, c4 = i & 3;
            size_t off = (size_t)(row0 + row) * HID + k0;
            cpa16(bufA + row * 80 + c4 * 16, (const char*)(g_HIDH + off) + c4 * 16);
        }
#pragma unroll
        for (int j = 0; j < 2; ++j) {  // B: 32 k-rows x 256 B
            int i = tid + j * 256;
            int r = (i >> 4) & 31, cc = i & 15;
            const char* g = (const char*)(g_W3H + wb + (size_t)(k0 + r) * DIMD +
                                          ntile * 128 + cc * 8);
            cpa16(bufB + r * 256 + ((cc ^ (r & 7)) << 4), g);
        }
    };

    const int mw = wid >> 2, nw = wid & 3;
    const int m0 = mw * 64, n0 = nw * 32;
    float acc[4][4][4];
#pragma unroll
    for (int a = 0; a < 4; ++a)
#pragma unroll
        for (int b = 0; b < 4; ++b)
#pragma unroll
            for (int r = 0; r < 4; ++r) acc[a][b][r] = 0.f;

    issue(0); cp_commit();
    issue(1); cp_commit();

    for (int c = 0; c < NCH2; ++c) {
        if (c + 2 < NCH2) issue(c + 2);
        cp_commit();
        cp_wait2();
        __syncthreads();
        const uint32_t bufA = sbase + (c & 3) * G2_STG;
        const uint32_t bufB = bufA + 10240;
#pragma unroll
        for (int ks = 0; ks < 32; ks += 16) {
            uint32_t ah[4][4];
#pragma unroll
            for (int mi = 0; mi < 4; ++mi)
                ldsm4(ah[mi], bufA + (m0 + mi * 16 + (lane & 15)) * 80 + ks * 2 + (lane >> 4) * 16);
            uint32_t bh[2][4];
            const int grp = lane >> 3;
            const int kr = ks + ((grp & 1) << 3) + (lane & 7);
#pragma unroll
            for (int gj = 0; gj < 2; ++gj) {
                int cc = ((n0 + (gj << 4)) >> 3) + (grp >> 1);
                ldsm4t(bh[gj], bufB + kr * 256 + ((cc ^ (kr & 7)) << 4));
            }
#pragma unroll
            for (int mi = 0; mi < 4; ++mi)
#pragma unroll
                for (int nj = 0; nj < 4; ++nj)
                    mma16816(acc[mi][nj], ah[mi], &bh[nj >> 1][(nj & 1) * 2]);
        }
    }

#pragma unroll
    for (int mi = 0; mi < 4; ++mi)
#pragma unroll
        for (int h = 0; h < 2; ++h) {
            int rl = m0 + mi * 16 + h * 8 + (lane >> 2);
            int lr = mtile * 128 + rl;
            if (lr < ne) {
                size_t rowb = (size_t)(row0 + rl) * DIMD + ntile * 128;
#pragma unroll
                for (int nj = 0; nj < 4; ++nj) {
                    int col = n0 + nj * 8 + 2 * (lane & 3);
                    float2 v = make_float2(acc[mi][nj][h * 2], acc[mi][nj][h * 2 + 1]);
                    *(float2*)&g_OUTP[rowb + col] = v;
                }
            }
        }
}

// ---------------- combine ---------------------------------------------------
__global__ void combine_kernel(float* __restrict__ out, int out_size) {
    const int t = blockIdx.x, tid = threadIdx.x;
    float4 acc = make_float4(0.f, 0.f, 0.f, 0.f);
#pragma unroll
    for (int k = 0; k < TOPK; ++k) {
        int e = g_tok_e[t * TOPK + k];
        int row = g_offs[e] + g_tok_pos[t * TOPK + k];
        float w = g_tok_w[t * TOPK + k];
        float4 v = ((const float4*)(g_OUTP + (size_t)row * DIMD))[tid];
        acc.x += w * v.x; acc.y += w * v.y; acc.z += w * v.z; acc.w += w * v.w;
    }
    ((float4*)(out + (size_t)t * DIMD))[tid] = acc;
    if (t == 0 && tid == 0 && out_size > NTOK * DIMD)
        out[NTOK * DIMD] = 0.01f * g_aux / (float)(NTOK * NEXP);
}

// ---------------- launch -----------------------------------------------------
extern "C" void kernel_launch(void* const* d_in, const int* in_sizes, int n_in,
                              void* d_out, int out_size) {
    const float *x = 0, *rw = 0, *rb = 0, *w12 = 0, *w3 = 0;
    for (int i = 0; i < n_in; ++i) {
        switch (in_sizes[i]) {
            case 4194304:  x   = (const float*)d_in[i]; break;
            case 8192:     rw  = (const float*)d_in[i]; break;
            case 8:        rb  = (const float*)d_in[i]; break;
            case 67108864: w12 = (const float*)d_in[i]; break;
            case 33554432: w3  = (const float*)d_in[i]; break;
        }
    }
    if (!x || !rw || !rb || !w12 || !w3) {
        x = (const float*)d_in[0]; rw = (const float*)d_in[1]; rb = (const float*)d_in[2];
        w12 = (const float*)d_in[3]; w3 = (const float*)d_in[4];
    }
    float* out = (float*)d_out;

    cudaFuncSetAttribute(gemm1_kernel, cudaFuncAttributeMaxDynamicSharedMemorySize, G1_DYN);
    cudaFuncSetAttribute(gemm2_kernel, cudaFuncAttributeMaxDynamicSharedMemorySize, G2_DYN);

    prep_kernel<<<102401, 256>>>((const float4*)x, (const float4*)w12, (const float4*)w3);
    router_kernel<<<NTOK / 4, 128>>>(x, rw, rb);
    prefix_kernel<<<1, 1>>>();
    gemm1_kernel<<<dim3(64, 32, NEXP), 256, G1_DYN>>>();
    gemm2_kernel<<<dim3(32, 8, NEXP), 256, G2_DYN>>>();
    combine_kernel<<<NTOK, 256>>>(out, out_size);
}